// round 1
// baseline (speedup 1.0000x reference)
#include <cuda_runtime.h>
#include <cuda_fp16.h>
#include <mma.h>
#include <math.h>

using namespace nvcuda;

#define NTOK  4096
#define HDIM  1024
#define IDIM  1024
#define NEXP  8
#define TOPK  4
#define GUDIM 2048   // 2*I interleaved gate/up

// GEMM tiling
#define MT      128
#define NT_TILE 128
#define KT      64

// ---------------- device scratch (allocation-free rule: __device__ globals) ---------
__device__ __align__(16) __half g_xh [(size_t)NTOK * HDIM];                 // 8 MB
__device__ __align__(16) __half g_w1h[(size_t)NEXP * HDIM * GUDIM];         // 32 MB
__device__ __align__(16) __half g_w2h[(size_t)NEXP * IDIM * HDIM];          // 16 MB
__device__ __align__(16) __half g_act[(size_t)NEXP * NTOK * IDIM];          // 64 MB
__device__ __align__(16) float  g_ebuf[(size_t)NTOK * TOPK * HDIM];         // 64 MB
__device__ int g_count[NEXP];
__device__ int g_assign[NEXP * NTOK];   // packed token*4+slot, bucketed by expert

// ---------------- tiny utility kernels ---------------------------------------------
__global__ void zero_counts_kernel() {
    if (threadIdx.x < NEXP) g_count[threadIdx.x] = 0;
}

__global__ void cvt_x_kernel(const float* __restrict__ s) {
    int stride = gridDim.x * blockDim.x;
    int n4 = NTOK * HDIM / 4;
    for (int i = blockIdx.x * blockDim.x + threadIdx.x; i < n4; i += stride) {
        float4 v = ((const float4*)s)[i];
        __half2* d = (__half2*)(g_xh + (size_t)i * 4);
        d[0] = __floats2half2_rn(v.x, v.y);
        d[1] = __floats2half2_rn(v.z, v.w);
    }
}

__global__ void cvt_w1_kernel(const float* __restrict__ s) {
    int stride = gridDim.x * blockDim.x;
    int n4 = NEXP * HDIM * GUDIM / 4;
    for (int i = blockIdx.x * blockDim.x + threadIdx.x; i < n4; i += stride) {
        float4 v = ((const float4*)s)[i];
        __half2* d = (__half2*)(g_w1h + (size_t)i * 4);
        d[0] = __floats2half2_rn(v.x, v.y);
        d[1] = __floats2half2_rn(v.z, v.w);
    }
}

__global__ void cvt_w2_kernel(const float* __restrict__ s) {
    int stride = gridDim.x * blockDim.x;
    int n4 = NEXP * IDIM * HDIM / 4;
    for (int i = blockIdx.x * blockDim.x + threadIdx.x; i < n4; i += stride) {
        float4 v = ((const float4*)s)[i];
        __half2* d = (__half2*)(g_w2h + (size_t)i * 4);
        d[0] = __floats2half2_rn(v.x, v.y);
        d[1] = __floats2half2_rn(v.z, v.w);
    }
}

// ---------------- router: 1 warp per token ------------------------------------------
__global__ void router_kernel(const float* __restrict__ x,
                              const float* __restrict__ rw,
                              const float* __restrict__ rb,
                              float* __restrict__ ew_out) {
    int warp = (blockIdx.x * blockDim.x + threadIdx.x) >> 5;
    int lane = threadIdx.x & 31;
    if (warp >= NTOK) return;
    const float* xr = x + (size_t)warp * HDIM;

    float acc[NEXP];
#pragma unroll
    for (int e = 0; e < NEXP; e++) acc[e] = 0.f;

    for (int h = lane; h < HDIM; h += 32) {
        float xv = xr[h];
#pragma unroll
        for (int e = 0; e < NEXP; e++) acc[e] += xv * rw[e * HDIM + h];
    }
#pragma unroll
    for (int e = 0; e < NEXP; e++) {
#pragma unroll
        for (int off = 16; off; off >>= 1)
            acc[e] += __shfl_xor_sync(0xffffffffu, acc[e], off);
    }

    if (lane == 0) {
        float lg[NEXP];
#pragma unroll
        for (int e = 0; e < NEXP; e++) lg[e] = acc[e] + rb[e];

        int   idx[TOPK];
        float val[TOPK];
        bool  used[NEXP];
#pragma unroll
        for (int e = 0; e < NEXP; e++) used[e] = false;

        // top-k, ties -> lowest index (matches jax.lax.top_k)
        for (int k = 0; k < TOPK; k++) {
            float best = -INFINITY; int bi = 0;
            for (int e = 0; e < NEXP; e++)
                if (!used[e] && lg[e] > best) { best = lg[e]; bi = e; }
            used[bi] = true; idx[k] = bi; val[k] = best;
        }
        // softmax over the 4 selected (val[0] is max)
        float m = val[0], s = 0.f, w[TOPK];
        for (int k = 0; k < TOPK; k++) { w[k] = expf(val[k] - m); s += w[k]; }
        float inv = 1.f / s;
        for (int k = 0; k < TOPK; k++) {
            w[k] *= inv;
            ew_out[warp * TOPK + k] = w[k];
            int p = atomicAdd(&g_count[idx[k]], 1);
            g_assign[idx[k] * NTOK + p] = warp * 4 + k;
        }
    }
}

// ---------------- GEMM1: gate_up = gather(x) @ w1[e] + b1 ; SwiGLU -> g_act ---------
__global__ __launch_bounds__(256, 2)
void gemm1_kernel(const float* __restrict__ b1) {
    const int e    = blockIdx.z;
    const int cnt  = g_count[e];
    const int row0 = blockIdx.y * MT;
    if (row0 >= cnt) return;
    const int col0 = blockIdx.x * NT_TILE;   // gate_up column base

    __shared__ __align__(16) __half sA[MT][KT + 8];
    __shared__ __align__(16) __half sB[KT][NT_TILE + 8];
    __shared__ int   s_tok[MT];
    __shared__ __align__(16) float s_stage[8][16][20];

    const int tid = threadIdx.x, lane = tid & 31, warp = tid >> 5;
    const int wm = warp >> 1, wn = warp & 1;   // 4 x 2 warp grid, warp tile 32x64

    if (tid < MT) {
        int r = row0 + tid;
        s_tok[tid] = (r < cnt) ? (g_assign[e * NTOK + r] >> 2) : -1;
    }
    __syncthreads();

    wmma::fragment<wmma::accumulator, 16, 16, 16, float> c[2][4];
#pragma unroll
    for (int i = 0; i < 2; i++)
#pragma unroll
        for (int j = 0; j < 4; j++) wmma::fill_fragment(c[i][j], 0.0f);

    const __half* Bb = g_w1h + (size_t)e * HDIM * GUDIM + col0;

    for (int kt = 0; kt < HDIM; kt += KT) {
        // A: 128 rows x 64 halves = 1024 float4
#pragma unroll
        for (int i = 0; i < 4; i++) {
            int v = tid + i * 256;
            int r = v >> 3, c8 = v & 7;
            int tok = s_tok[r];
            float4 d;
            if (tok >= 0) d = *(const float4*)(g_xh + (size_t)tok * HDIM + kt + c8 * 8);
            else          d = make_float4(0.f, 0.f, 0.f, 0.f);
            *(float4*)&sA[r][c8 * 8] = d;
        }
        // B: 64 rows x 128 halves = 1024 float4
#pragma unroll
        for (int i = 0; i < 4; i++) {
            int v = tid + i * 256;
            int r = v >> 4, c16 = v & 15;
            *(float4*)&sB[r][c16 * 8] =
                *(const float4*)(Bb + (size_t)(kt + r) * GUDIM + c16 * 8);
        }
        __syncthreads();

#pragma unroll
        for (int kk = 0; kk < KT; kk += 16) {
            wmma::fragment<wmma::matrix_a, 16, 16, 16, half, wmma::row_major> a[2];
            wmma::fragment<wmma::matrix_b, 16, 16, 16, half, wmma::row_major> b[4];
#pragma unroll
            for (int i = 0; i < 2; i++)
                wmma::load_matrix_sync(a[i], &sA[wm * 32 + i * 16][kk], KT + 8);
#pragma unroll
            for (int j = 0; j < 4; j++)
                wmma::load_matrix_sync(b[j], &sB[kk][wn * 64 + j * 16], NT_TILE + 8);
#pragma unroll
            for (int i = 0; i < 2; i++)
#pragma unroll
                for (int j = 0; j < 4; j++)
                    wmma::mma_sync(c[i][j], a[i], b[j], c[i][j]);
        }
        __syncthreads();
    }

    // epilogue: bias + SwiGLU(OAI), act col = gate_up col / 2
#pragma unroll
    for (int i = 0; i < 2; i++)
#pragma unroll
        for (int j = 0; j < 4; j++) {
            wmma::store_matrix_sync(&s_stage[warp][0][0], c[i][j], 20, wmma::mem_row_major);
            __syncwarp();
            int rt = wm * 32 + i * 16;
            int ct = col0 + wn * 64 + j * 16;
#pragma unroll
            for (int t = lane; t < 128; t += 32) {   // 16 rows x 8 pairs
                int rr = t >> 3, pp = t & 7;
                int r = row0 + rt + rr;
                if (r < cnt) {
                    int gc = ct + pp * 2;
                    float g = s_stage[warp][rr][pp * 2]     + b1[e * GUDIM + gc];
                    float u = s_stage[warp][rr][pp * 2 + 1] + b1[e * GUDIM + gc + 1];
                    g = fminf(g, 7.0f);
                    u = fminf(fmaxf(u, -7.0f), 7.0f);
                    float glu = g / (1.0f + expf(-1.702f * g));
                    g_act[((size_t)e * NTOK + r) * IDIM + (gc >> 1)] =
                        __float2half((u + 1.0f) * glu);
                }
            }
            __syncwarp();
        }
}

// ---------------- GEMM2: ebuf[token][slot] = act @ w2[e] + b2 -----------------------
__global__ __launch_bounds__(256, 2)
void gemm2_kernel(const float* __restrict__ b2) {
    const int e    = blockIdx.z;
    const int cnt  = g_count[e];
    const int row0 = blockIdx.y * MT;
    if (row0 >= cnt) return;
    const int col0 = blockIdx.x * NT_TILE;

    __shared__ __align__(16) __half sA[MT][KT + 8];
    __shared__ __align__(16) __half sB[KT][NT_TILE + 8];
    __shared__ int   s_asn[MT];
    __shared__ __align__(16) float s_stage[8][16][20];

    const int tid = threadIdx.x, lane = tid & 31, warp = tid >> 5;
    const int wm = warp >> 1, wn = warp & 1;

    if (tid < MT) {
        int r = row0 + tid;
        s_asn[tid] = (r < cnt) ? g_assign[e * NTOK + r] : -1;
    }
    __syncthreads();

    wmma::fragment<wmma::accumulator, 16, 16, 16, float> c[2][4];
#pragma unroll
    for (int i = 0; i < 2; i++)
#pragma unroll
        for (int j = 0; j < 4; j++) wmma::fill_fragment(c[i][j], 0.0f);

    const __half* Bb = g_w2h + (size_t)e * IDIM * HDIM + col0;
    const __half* Ab = g_act + ((size_t)e * NTOK + row0) * IDIM;

    for (int kt = 0; kt < IDIM; kt += KT) {
#pragma unroll
        for (int i = 0; i < 4; i++) {
            int v = tid + i * 256;
            int r = v >> 3, c8 = v & 7;
            float4 d;
            if (s_asn[r] >= 0) d = *(const float4*)(Ab + (size_t)r * IDIM + kt + c8 * 8);
            else               d = make_float4(0.f, 0.f, 0.f, 0.f);
            *(float4*)&sA[r][c8 * 8] = d;
        }
#pragma unroll
        for (int i = 0; i < 4; i++) {
            int v = tid + i * 256;
            int r = v >> 4, c16 = v & 15;
            *(float4*)&sB[r][c16 * 8] =
                *(const float4*)(Bb + (size_t)(kt + r) * HDIM + c16 * 8);
        }
        __syncthreads();

#pragma unroll
        for (int kk = 0; kk < KT; kk += 16) {
            wmma::fragment<wmma::matrix_a, 16, 16, 16, half, wmma::row_major> a[2];
            wmma::fragment<wmma::matrix_b, 16, 16, 16, half, wmma::row_major> b[4];
#pragma unroll
            for (int i = 0; i < 2; i++)
                wmma::load_matrix_sync(a[i], &sA[wm * 32 + i * 16][kk], KT + 8);
#pragma unroll
            for (int j = 0; j < 4; j++)
                wmma::load_matrix_sync(b[j], &sB[kk][wn * 64 + j * 16], NT_TILE + 8);
#pragma unroll
            for (int i = 0; i < 2; i++)
#pragma unroll
                for (int j = 0; j < 4; j++)
                    wmma::mma_sync(c[i][j], a[i], b[j], c[i][j]);
        }
        __syncthreads();
    }

    // epilogue: + b2, scatter to ebuf[token*4+slot]
#pragma unroll
    for (int i = 0; i < 2; i++)
#pragma unroll
        for (int j = 0; j < 4; j++) {
            wmma::store_matrix_sync(&s_stage[warp][0][0], c[i][j], 20, wmma::mem_row_major);
            __syncwarp();
            int rt = wm * 32 + i * 16;
            int ct = col0 + wn * 64 + j * 16;
#pragma unroll
            for (int t = lane; t < 256; t += 32) {   // 16x16 elems
                int rr = t >> 4, cc = t & 15;
                int a = s_asn[rt + rr];
                if (a >= 0) {
                    g_ebuf[(size_t)a * HDIM + ct + cc] =
                        s_stage[warp][rr][cc] + b2[e * HDIM + ct + cc];
                }
            }
            __syncwarp();
        }
}

// ---------------- combine: out[t] = sum_k w[t][k] * ebuf[t][k] (fixed order) --------
__global__ void combine_kernel(float* __restrict__ out) {
    const float* ew = out + (size_t)NTOK * HDIM;  // router wrote these earlier
    int stride = gridDim.x * blockDim.x;
    int n4 = NTOK * HDIM / 4;
    for (int v = blockIdx.x * blockDim.x + threadIdx.x; v < n4; v += stride) {
        int t  = v >> 8;        // 256 float4 per token
        int hc = v & 255;
        float w0 = ew[t * 4 + 0], w1v = ew[t * 4 + 1];
        float w2v = ew[t * 4 + 2], w3 = ew[t * 4 + 3];
        const float4* e0 = (const float4*)(g_ebuf + (size_t)(t * 4 + 0) * HDIM);
        const float4* e1 = (const float4*)(g_ebuf + (size_t)(t * 4 + 1) * HDIM);
        const float4* e2 = (const float4*)(g_ebuf + (size_t)(t * 4 + 2) * HDIM);
        const float4* e3 = (const float4*)(g_ebuf + (size_t)(t * 4 + 3) * HDIM);
        float4 r0 = e0[hc], r1 = e1[hc], r2 = e2[hc], r3 = e3[hc];
        float4 o;
        o.x = w0 * r0.x + w1v * r1.x + w2v * r2.x + w3 * r3.x;
        o.y = w0 * r0.y + w1v * r1.y + w2v * r2.y + w3 * r3.y;
        o.z = w0 * r0.z + w1v * r1.z + w2v * r2.z + w3 * r3.z;
        o.w = w0 * r0.w + w1v * r1.w + w2v * r2.w + w3 * r3.w;
        ((float4*)out)[v] = o;
    }
}

// ---------------- launch ------------------------------------------------------------
extern "C" void kernel_launch(void* const* d_in, const int* in_sizes, int n_in,
                              void* d_out, int out_size) {
    const float* x  = (const float*)d_in[0];
    const float* rw = (const float*)d_in[1];
    const float* rb = (const float*)d_in[2];
    const float* w1 = (const float*)d_in[3];
    const float* b1 = (const float*)d_in[4];
    const float* w2 = (const float*)d_in[5];
    const float* b2 = (const float*)d_in[6];
    float* out = (float*)d_out;

    zero_counts_kernel<<<1, 32>>>();
    cvt_x_kernel <<<1024, 256>>>(x);
    cvt_w1_kernel<<<2048, 256>>>(w1);
    cvt_w2_kernel<<<2048, 256>>>(w2);

    router_kernel<<<NTOK / 8, 256>>>(x, rw, rb, out + (size_t)NTOK * HDIM);

    gemm1_kernel<<<dim3(GUDIM / NT_TILE, NTOK / MT, NEXP), 256>>>(b1);
    gemm2_kernel<<<dim3(HDIM  / NT_TILE, NTOK / MT, NEXP), 256>>>(b2);

    combine_kernel<<<2048, 256>>>(out);
}

// round 3
// speedup vs baseline: 1.4045x; 1.4045x over previous
#include <cuda_runtime.h>
#include <cuda_fp16.h>
#include <mma.h>
#include <cstdint>
#include <math.h>

#if defined(__CUDA_ARCH_FEAT_SM103_ALL) || defined(__CUDA_ARCH_FEAT_SM100_ALL) || defined(__CUDA_ARCH_FEAT_SM101_ALL)
#define HAS_TC 1
#else
#define HAS_TC 0
#endif

#define NTOK  4096
#define HDIM  1024
#define IDIM  1024
#define NEXP  8
#define TOPK  4
#define GUDIM 2048

#define MT 128
#define NT 128
#define KT 64                    // halves per K-chunk (128 B/row = SW128 atom)
#define NCHUNK 16                // 1024 / 64

// idesc: dtype=F32(1<<4), atype=btype=F16(0), N=128 -> (N/8)<<17, M=128 -> (M/16)<<24
#define IDESC_F16 ((1u << 4) | ((NT / 8) << 17) | ((MT / 16) << 24))

// dynamic smem layout (tcgen05 path)
#define SM_TOK    64
#define SM_BUF    1024
#define BUF_SZ    32768          // A 16KB + B 16KB
#define SMEM_TOTAL (SM_BUF + 2 * BUF_SZ)   // 66560 (fallback fits inside too)

// ---------------- device scratch ----------------------------------------------------
__device__ __align__(16) __half g_xh [(size_t)NTOK * HDIM];
__device__ __align__(16) __half g_w1h[(size_t)NEXP * GUDIM * HDIM];   // [e][n][k]
__device__ __align__(16) __half g_w2h[(size_t)NEXP * HDIM * IDIM];    // [e][n][k]
__device__ __align__(16) __half g_act[(size_t)NEXP * NTOK * IDIM];
__device__ __align__(16) float  g_ebuf[(size_t)NTOK * TOPK * HDIM];
__device__ int g_count[NEXP];
__device__ int g_assign[NEXP * NTOK];

// ---------------- helpers -----------------------------------------------------------
__device__ __forceinline__ uint32_t smem_u32(const void* p) {
    uint32_t a;
    asm("{ .reg .u64 t; cvta.to.shared.u64 t, %1; cvt.u32.u64 %0, t; }" : "=r"(a) : "l"(p));
    return a;
}
__device__ __forceinline__ uint32_t sw128(uint32_t off) {
    return off ^ ((off >> 3) & 0x70);
}

#if HAS_TC
__device__ __forceinline__ uint32_t elect_one() {
    uint32_t pred;
    asm volatile("{\n\t.reg .pred p;\n\telect.sync _|p, 0xFFFFFFFF;\n\t"
                 "selp.b32 %0, 1, 0, p;\n\t}" : "=r"(pred));
    return pred;
}
#define TC_ALLOC(sa, n)  asm volatile("tcgen05.alloc.cta_group::1.sync.aligned.shared::cta.b32 [%0], %1;" :: "r"(sa), "r"(n) : "memory")
#define TC_DEALLOC(t, n) asm volatile("tcgen05.dealloc.cta_group::1.sync.aligned.b32 %0, %1;" :: "r"(t), "r"(n))
#define TC_RELINQ()      asm volatile("tcgen05.relinquish_alloc_permit.cta_group::1.sync.aligned;")
#define TC_COMMIT(mb)    asm volatile("tcgen05.commit.cta_group::1.mbarrier::arrive::one.shared::cluster.b64 [%0];" :: "r"(mb) : "memory")
#define TC_FENCE_AFTER()  asm volatile("tcgen05.fence::after_thread_sync;" ::: "memory")
#define TC_FENCE_BEFORE() asm volatile("tcgen05.fence::before_thread_sync;" ::: "memory")
#define TC_WAIT_LD()     asm volatile("tcgen05.wait::ld.sync.aligned;" ::: "memory")
#define FENCE_ASYNC()    asm volatile("fence.proxy.async.shared::cta;" ::: "memory")
#define MBAR_INIT(mb, n) asm volatile("mbarrier.init.shared.b64 [%0], %1;" :: "r"(mb), "r"(n) : "memory")

__device__ __forceinline__ void mbar_wait(uint32_t mb, uint32_t parity) {
    uint32_t done;
    asm volatile("{\n\t.reg .pred p;\n\t"
                 "mbarrier.try_wait.parity.acquire.cta.shared::cta.b64 p, [%1], %2;\n\t"
                 "selp.b32 %0, 1, 0, p;\n\t}"
                 : "=r"(done) : "r"(mb), "r"(parity) : "memory");
    if (!done) {
        asm volatile("{\n\t.reg .pred P1;\n\t"
                     "W_%=:\n\t"
                     "mbarrier.try_wait.parity.acquire.cta.shared::cta.b64 P1, [%0], %1, 0x989680;\n\t"
                     "@P1 bra.uni D_%=;\n\t"
                     "bra.uni W_%=;\n\t"
                     "D_%=:\n\t}"
                     :: "r"(mb), "r"(parity) : "memory");
    }
}
__device__ __forceinline__ uint64_t make_desc(uint32_t addr) {
    return ((uint64_t)2 << 61) | ((uint64_t)1 << 46) | ((uint64_t)64 << 32) |
           ((uint64_t)1 << 16) | ((uint64_t)(addr >> 4) & 0x3FFF);
}
__device__ __forceinline__ void mma_f16_ss(uint32_t d, uint64_t ad, uint64_t bd,
                                           uint32_t idesc, uint32_t en) {
    asm volatile("{\n\t.reg .pred p;\n\t"
                 "setp.ne.u32 p, %5, 0;\n\t"
                 "tcgen05.mma.cta_group::1.kind::f16 [%0], %1, %2, %3, {%4, %4, %4, %4}, p;\n\t}"
                 :: "r"(d), "l"(ad), "l"(bd), "r"(idesc), "r"(0u), "r"(en)
                 : "memory");
}
#define TC_LD_X32(r, a) \
    asm volatile("tcgen05.ld.sync.aligned.32x32b.x32.b32 " \
        "{%0,%1,%2,%3,%4,%5,%6,%7,%8,%9,%10,%11,%12,%13,%14,%15," \
        "%16,%17,%18,%19,%20,%21,%22,%23,%24,%25,%26,%27,%28,%29,%30,%31}, [%32];" \
        : "=r"((r)[0]),"=r"((r)[1]),"=r"((r)[2]),"=r"((r)[3]),"=r"((r)[4]),"=r"((r)[5]),"=r"((r)[6]),"=r"((r)[7]), \
          "=r"((r)[8]),"=r"((r)[9]),"=r"((r)[10]),"=r"((r)[11]),"=r"((r)[12]),"=r"((r)[13]),"=r"((r)[14]),"=r"((r)[15]), \
          "=r"((r)[16]),"=r"((r)[17]),"=r"((r)[18]),"=r"((r)[19]),"=r"((r)[20]),"=r"((r)[21]),"=r"((r)[22]),"=r"((r)[23]), \
          "=r"((r)[24]),"=r"((r)[25]),"=r"((r)[26]),"=r"((r)[27]),"=r"((r)[28]),"=r"((r)[29]),"=r"((r)[30]),"=r"((r)[31]) \
        : "r"(a))
#endif  // HAS_TC

// ---------------- tiny utility kernels ----------------------------------------------
__global__ void zero_counts_kernel() {
    if (threadIdx.x < NEXP) g_count[threadIdx.x] = 0;
}

__global__ void cvt_x_kernel(const float* __restrict__ s) {
    int stride = gridDim.x * blockDim.x;
    int n4 = NTOK * HDIM / 4;
    for (int i = blockIdx.x * blockDim.x + threadIdx.x; i < n4; i += stride) {
        float4 v = ((const float4*)s)[i];
        __half2* d = (__half2*)(g_xh + (size_t)i * 4);
        d[0] = __floats2half2_rn(v.x, v.y);
        d[1] = __floats2half2_rn(v.z, v.w);
    }
}

// transpose-convert: s [z][K][N] fp32 -> d [z][N][K] fp16
__global__ void cvt_t_kernel(const float* __restrict__ s, __half* __restrict__ d,
                             int K, int N) {
    __shared__ float t[32][33];
    int n0 = blockIdx.x * 32, k0 = blockIdx.y * 32, z = blockIdx.z;
    const float* sp = s + (size_t)z * K * N;
    __half* dp = d + (size_t)z * K * N;
    int tx = threadIdx.x, ty = threadIdx.y;
#pragma unroll
    for (int i = 0; i < 32; i += 8)
        t[ty + i][tx] = sp[(size_t)(k0 + ty + i) * N + n0 + tx];
    __syncthreads();
#pragma unroll
    for (int i = 0; i < 32; i += 8)
        dp[(size_t)(n0 + ty + i) * K + k0 + tx] = __float2half(t[tx][ty + i]);
}

// ---------------- router ------------------------------------------------------------
__global__ void router_kernel(const float* __restrict__ x,
                              const float* __restrict__ rw,
                              const float* __restrict__ rb,
                              float* __restrict__ ew_out) {
    int warp = (blockIdx.x * blockDim.x + threadIdx.x) >> 5;
    int lane = threadIdx.x & 31;
    if (warp >= NTOK) return;
    const float* xr = x + (size_t)warp * HDIM;

    float acc[NEXP];
#pragma unroll
    for (int e = 0; e < NEXP; e++) acc[e] = 0.f;
    for (int h = lane; h < HDIM; h += 32) {
        float xv = xr[h];
#pragma unroll
        for (int e = 0; e < NEXP; e++) acc[e] += xv * rw[e * HDIM + h];
    }
#pragma unroll
    for (int e = 0; e < NEXP; e++) {
#pragma unroll
        for (int off = 16; off; off >>= 1)
            acc[e] += __shfl_xor_sync(0xffffffffu, acc[e], off);
    }
    if (lane == 0) {
        float lg[NEXP];
#pragma unroll
        for (int e = 0; e < NEXP; e++) lg[e] = acc[e] + rb[e];
        int idx[TOPK]; float val[TOPK]; bool used[NEXP];
#pragma unroll
        for (int e = 0; e < NEXP; e++) used[e] = false;
        for (int k = 0; k < TOPK; k++) {
            float best = -INFINITY; int bi = 0;
            for (int e = 0; e < NEXP; e++)
                if (!used[e] && lg[e] > best) { best = lg[e]; bi = e; }
            used[bi] = true; idx[k] = bi; val[k] = best;
        }
        float m = val[0], s = 0.f, w[TOPK];
        for (int k = 0; k < TOPK; k++) { w[k] = expf(val[k] - m); s += w[k]; }
        float inv = 1.f / s;
        for (int k = 0; k < TOPK; k++) {
            w[k] *= inv;
            ew_out[warp * TOPK + k] = w[k];
            int p = atomicAdd(&g_count[idx[k]], 1);
            g_assign[idx[k] * NTOK + p] = warp * 4 + k;
        }
    }
}

// ====================================================================================
// GEMM1: act = SwiGLU(gather(x) @ w1^T + b1)
// ====================================================================================
__global__ __launch_bounds__(256)
void gemm1_kernel(const float* __restrict__ b1) {
    extern __shared__ char smem[];
    const int e    = blockIdx.z;
    const int cnt  = g_count[e];
    const int row0 = blockIdx.y * MT;
    if (row0 >= cnt) return;
    const int col0 = blockIdx.x * NT;
    const int tid = threadIdx.x, lane = tid & 31, wid = tid >> 5;

#if HAS_TC
    uint32_t sb = smem_u32(smem);
    int* s_tok = (int*)(smem + SM_TOK);
    if (wid == 0) { TC_ALLOC(sb, 128); TC_RELINQ(); }
    if (tid == 0) { MBAR_INIT(sb + 8, 1); MBAR_INIT(sb + 16, 1); }
    if (tid < 128) {
        int r = row0 + tid;
        s_tok[tid] = (r < cnt) ? (g_assign[e * NTOK + r] >> 2) : -1;
    }
    __syncthreads();
    uint32_t tmem;
    asm volatile("ld.shared.b32 %0, [%1];" : "=r"(tmem) : "r"(sb));

    {   // preload chunk 0
        char* bufA = smem + SM_BUF;
        char* bufB = bufA + 16384;
#pragma unroll
        for (int i = 0; i < 4; i++) {
            int v = tid + i * 256, r = v >> 3, c8 = v & 7;
            int tok = s_tok[r];
            float4 d = (tok >= 0) ? *(const float4*)(g_xh + (size_t)tok * HDIM + c8 * 8)
                                  : make_float4(0.f, 0.f, 0.f, 0.f);
            *(float4*)(bufA + sw128(r * 128 + c8 * 16)) = d;
            *(float4*)(bufB + sw128(r * 128 + c8 * 16)) =
                *(const float4*)(g_w1h + ((size_t)e * GUDIM + col0 + r) * HDIM + c8 * 8);
        }
    }
    __syncthreads();

    for (int c = 0; c < NCHUNK; c++) {
        int p = c & 1;
        if (wid == 0 && elect_one()) {
            FENCE_ASYNC();
            uint64_t ad = make_desc(sb + SM_BUF + p * BUF_SZ);
            uint64_t bd = make_desc(sb + SM_BUF + p * BUF_SZ + 16384);
#pragma unroll
            for (int s = 0; s < 4; s++)
                mma_f16_ss(tmem, ad + s * 2, bd + s * 2, IDESC_F16, (c > 0 || s > 0) ? 1u : 0u);
            TC_COMMIT(sb + 8 + p * 8);
        }
        if (c + 1 < NCHUNK) {
            int np = (c + 1) & 1;
            if (c + 1 >= 2) mbar_wait(sb + 8 + np * 8, (((c + 1) >> 1) - 1) & 1);
            int kt = (c + 1) * KT;
            char* bufA = smem + SM_BUF + np * BUF_SZ;
            char* bufB = bufA + 16384;
#pragma unroll
            for (int i = 0; i < 4; i++) {
                int v = tid + i * 256, r = v >> 3, c8 = v & 7;
                int tok = s_tok[r];
                float4 d = (tok >= 0) ? *(const float4*)(g_xh + (size_t)tok * HDIM + kt + c8 * 8)
                                      : make_float4(0.f, 0.f, 0.f, 0.f);
                *(float4*)(bufA + sw128(r * 128 + c8 * 16)) = d;
                *(float4*)(bufB + sw128(r * 128 + c8 * 16)) =
                    *(const float4*)(g_w1h + ((size_t)e * GUDIM + col0 + r) * HDIM + kt + c8 * 8);
            }
            __syncthreads();
        }
    }
    mbar_wait(sb + 8 + ((NCHUNK - 1) & 1) * 8, ((NCHUNK - 1) >> 1) & 1);
    TC_FENCE_AFTER();

    // epilogue: 8 warps; warp w -> subpartition w&3 (rows), col-half w>>2
    {
        int sub = wid & 3, ch = wid >> 2;
        int r = row0 + sub * 32 + lane;
        bool valid = (r < cnt);
        const float* bb = b1 + e * GUDIM + col0;
#pragma unroll
        for (int cbi = 0; cbi < 2; cbi++) {
            int cb = ch * 2 + cbi;
            uint32_t regs[32];
            TC_LD_X32(regs, tmem + cb * 32);
            TC_WAIT_LD();
            if (valid) {
                __align__(16) __half hv[16];
#pragma unroll
                for (int j = 0; j < 16; j++) {
                    float g = __uint_as_float(regs[2 * j])     + bb[cb * 32 + 2 * j];
                    float u = __uint_as_float(regs[2 * j + 1]) + bb[cb * 32 + 2 * j + 1];
                    g = fminf(g, 7.0f);
                    u = fminf(fmaxf(u, -7.0f), 7.0f);
                    float glu = g / (1.0f + expf(-1.702f * g));
                    hv[j] = __float2half((u + 1.0f) * glu);
                }
                __half* dst = g_act + ((size_t)e * NTOK + r) * IDIM + (col0 >> 1) + cb * 16;
                *(int4*)dst       = *(int4*)hv;
                *(int4*)(dst + 8) = *(int4*)(hv + 8);
            }
        }
    }
    TC_FENCE_BEFORE();
    __syncthreads();
    if (wid == 0) TC_DEALLOC(tmem, 128);

#else  // ---------------- wmma fallback ----------------------------------------------
    using namespace nvcuda;
    int*    s_tok   = (int*)smem;
    __half* sA      = (__half*)(smem + 1024);                 // [128][72] row=token
    __half* sB      = (__half*)(smem + 1024 + 128 * 72 * 2);  // [128][72] row=n, col=k
    float*  s_stage = (float*)(smem + 1024 + 2 * 128 * 72 * 2);

    const int wm = wid >> 1, wn = wid & 1;
    if (tid < 128) {
        int r = row0 + tid;
        s_tok[tid] = (r < cnt) ? (g_assign[e * NTOK + r] >> 2) : -1;
    }
    __syncthreads();

    wmma::fragment<wmma::accumulator, 16, 16, 16, float> c[2][4];
#pragma unroll
    for (int i = 0; i < 2; i++)
#pragma unroll
        for (int j = 0; j < 4; j++) wmma::fill_fragment(c[i][j], 0.0f);

    const __half* Bb = g_w1h + ((size_t)e * GUDIM + col0) * HDIM;

    for (int kt = 0; kt < HDIM; kt += KT) {
#pragma unroll
        for (int i = 0; i < 4; i++) {
            int v = tid + i * 256, r = v >> 3, c8 = v & 7;
            int tok = s_tok[r];
            float4 d = (tok >= 0) ? *(const float4*)(g_xh + (size_t)tok * HDIM + kt + c8 * 8)
                                  : make_float4(0.f, 0.f, 0.f, 0.f);
            *(float4*)&sA[r * 72 + c8 * 8] = d;
            *(float4*)&sB[r * 72 + c8 * 8] =
                *(const float4*)(Bb + (size_t)r * HDIM + kt + c8 * 8);
        }
        __syncthreads();
#pragma unroll
        for (int kk = 0; kk < KT; kk += 16) {
            wmma::fragment<wmma::matrix_a, 16, 16, 16, half, wmma::row_major> a[2];
            wmma::fragment<wmma::matrix_b, 16, 16, 16, half, wmma::col_major> b[4];
#pragma unroll
            for (int i = 0; i < 2; i++)
                wmma::load_matrix_sync(a[i], &sA[(wm * 32 + i * 16) * 72 + kk], 72);
#pragma unroll
            for (int j = 0; j < 4; j++)
                wmma::load_matrix_sync(b[j], &sB[(wn * 64 + j * 16) * 72 + kk], 72);
#pragma unroll
            for (int i = 0; i < 2; i++)
#pragma unroll
                for (int j = 0; j < 4; j++)
                    wmma::mma_sync(c[i][j], a[i], b[j], c[i][j]);
        }
        __syncthreads();
    }

#pragma unroll
    for (int i = 0; i < 2; i++)
#pragma unroll
        for (int j = 0; j < 4; j++) {
            wmma::store_matrix_sync(&s_stage[wid * 320], c[i][j], 20, wmma::mem_row_major);
            __syncwarp();
            int rt = wm * 32 + i * 16;
            int ct = col0 + wn * 64 + j * 16;
#pragma unroll
            for (int t = lane; t < 128; t += 32) {
                int rr = t >> 3, pp = t & 7;
                int r = row0 + rt + rr;
                if (r < cnt) {
                    int gc = ct + pp * 2;
                    float g = s_stage[wid * 320 + rr * 20 + pp * 2]     + b1[e * GUDIM + gc];
                    float u = s_stage[wid * 320 + rr * 20 + pp * 2 + 1] + b1[e * GUDIM + gc + 1];
                    g = fminf(g, 7.0f);
                    u = fminf(fmaxf(u, -7.0f), 7.0f);
                    float glu = g / (1.0f + expf(-1.702f * g));
                    g_act[((size_t)e * NTOK + r) * IDIM + (gc >> 1)] =
                        __float2half((u + 1.0f) * glu);
                }
            }
            __syncwarp();
        }
#endif
}

// ====================================================================================
// GEMM2: ebuf[assign] = act @ w2^T + b2
// ====================================================================================
__global__ __launch_bounds__(256)
void gemm2_kernel(const float* __restrict__ b2) {
    extern __shared__ char smem[];
    const int e    = blockIdx.z;
    const int cnt  = g_count[e];
    const int row0 = blockIdx.y * MT;
    if (row0 >= cnt) return;
    const int col0 = blockIdx.x * NT;
    const int tid = threadIdx.x, lane = tid & 31, wid = tid >> 5;

#if HAS_TC
    uint32_t sb = smem_u32(smem);
    int* s_asn = (int*)(smem + SM_TOK);
    if (wid == 0) { TC_ALLOC(sb, 128); TC_RELINQ(); }
    if (tid == 0) { MBAR_INIT(sb + 8, 1); MBAR_INIT(sb + 16, 1); }
    if (tid < 128) {
        int r = row0 + tid;
        s_asn[tid] = (r < cnt) ? g_assign[e * NTOK + r] : -1;
    }
    __syncthreads();
    uint32_t tmem;
    asm volatile("ld.shared.b32 %0, [%1];" : "=r"(tmem) : "r"(sb));

    const __half* Ab = g_act + ((size_t)e * NTOK + row0) * IDIM;
    const __half* Bb = g_w2h + (size_t)e * HDIM * IDIM + (size_t)col0 * IDIM;

    {
        char* bufA = smem + SM_BUF;
        char* bufB = bufA + 16384;
#pragma unroll
        for (int i = 0; i < 4; i++) {
            int v = tid + i * 256, r = v >> 3, c8 = v & 7;
            float4 d = (s_asn[r] >= 0) ? *(const float4*)(Ab + (size_t)r * IDIM + c8 * 8)
                                       : make_float4(0.f, 0.f, 0.f, 0.f);
            *(float4*)(bufA + sw128(r * 128 + c8 * 16)) = d;
            *(float4*)(bufB + sw128(r * 128 + c8 * 16)) =
                *(const float4*)(Bb + (size_t)r * IDIM + c8 * 8);
        }
    }
    __syncthreads();

    for (int c = 0; c < NCHUNK; c++) {
        int p = c & 1;
        if (wid == 0 && elect_one()) {
            FENCE_ASYNC();
            uint64_t ad = make_desc(sb + SM_BUF + p * BUF_SZ);
            uint64_t bd = make_desc(sb + SM_BUF + p * BUF_SZ + 16384);
#pragma unroll
            for (int s = 0; s < 4; s++)
                mma_f16_ss(tmem, ad + s * 2, bd + s * 2, IDESC_F16, (c > 0 || s > 0) ? 1u : 0u);
            TC_COMMIT(sb + 8 + p * 8);
        }
        if (c + 1 < NCHUNK) {
            int np = (c + 1) & 1;
            if (c + 1 >= 2) mbar_wait(sb + 8 + np * 8, (((c + 1) >> 1) - 1) & 1);
            int kt = (c + 1) * KT;
            char* bufA = smem + SM_BUF + np * BUF_SZ;
            char* bufB = bufA + 16384;
#pragma unroll
            for (int i = 0; i < 4; i++) {
                int v = tid + i * 256, r = v >> 3, c8 = v & 7;
                float4 d = (s_asn[r] >= 0) ? *(const float4*)(Ab + (size_t)r * IDIM + kt + c8 * 8)
                                           : make_float4(0.f, 0.f, 0.f, 0.f);
                *(float4*)(bufA + sw128(r * 128 + c8 * 16)) = d;
                *(float4*)(bufB + sw128(r * 128 + c8 * 16)) =
                    *(const float4*)(Bb + (size_t)r * IDIM + kt + c8 * 8);
            }
            __syncthreads();
        }
    }
    mbar_wait(sb + 8 + ((NCHUNK - 1) & 1) * 8, ((NCHUNK - 1) >> 1) & 1);
    TC_FENCE_AFTER();

    {
        int sub = wid & 3, ch = wid >> 2;
        int rloc = sub * 32 + lane;
        int a = (row0 + rloc < cnt) ? s_asn[rloc] : -1;
        const float* bb = b2 + e * HDIM + col0;
#pragma unroll
        for (int cbi = 0; cbi < 2; cbi++) {
            int cb = ch * 2 + cbi;
            uint32_t regs[32];
            TC_LD_X32(regs, tmem + cb * 32);
            TC_WAIT_LD();
            if (a >= 0) {
                float* dst = g_ebuf + (size_t)a * HDIM + col0 + cb * 32;
#pragma unroll
                for (int j = 0; j < 8; j++) {
                    float4 o;
                    o.x = __uint_as_float(regs[4 * j + 0]) + bb[cb * 32 + 4 * j + 0];
                    o.y = __uint_as_float(regs[4 * j + 1]) + bb[cb * 32 + 4 * j + 1];
                    o.z = __uint_as_float(regs[4 * j + 2]) + bb[cb * 32 + 4 * j + 2];
                    o.w = __uint_as_float(regs[4 * j + 3]) + bb[cb * 32 + 4 * j + 3];
                    *(float4*)(dst + 4 * j) = o;
                }
            }
        }
    }
    TC_FENCE_BEFORE();
    __syncthreads();
    if (wid == 0) TC_DEALLOC(tmem, 128);

#else  // ---------------- wmma fallback ----------------------------------------------
    using namespace nvcuda;
    int*    s_asn   = (int*)smem;
    __half* sA      = (__half*)(smem + 1024);
    __half* sB      = (__half*)(smem + 1024 + 128 * 72 * 2);
    float*  s_stage = (float*)(smem + 1024 + 2 * 128 * 72 * 2);

    const int wm = wid >> 1, wn = wid & 1;
    if (tid < 128) {
        int r = row0 + tid;
        s_asn[tid] = (r < cnt) ? g_assign[e * NTOK + r] : -1;
    }
    __syncthreads();

    wmma::fragment<wmma::accumulator, 16, 16, 16, float> c[2][4];
#pragma unroll
    for (int i = 0; i < 2; i++)
#pragma unroll
        for (int j = 0; j < 4; j++) wmma::fill_fragment(c[i][j], 0.0f);

    const __half* Ab = g_act + ((size_t)e * NTOK + row0) * IDIM;
    const __half* Bb = g_w2h + (size_t)e * HDIM * IDIM + (size_t)col0 * IDIM;

    for (int kt = 0; kt < IDIM; kt += KT) {
#pragma unroll
        for (int i = 0; i < 4; i++) {
            int v = tid + i * 256, r = v >> 3, c8 = v & 7;
            float4 d = (s_asn[r] >= 0) ? *(const float4*)(Ab + (size_t)r * IDIM + kt + c8 * 8)
                                       : make_float4(0.f, 0.f, 0.f, 0.f);
            *(float4*)&sA[r * 72 + c8 * 8] = d;
            *(float4*)&sB[r * 72 + c8 * 8] =
                *(const float4*)(Bb + (size_t)r * IDIM + kt + c8 * 8);
        }
        __syncthreads();
#pragma unroll
        for (int kk = 0; kk < KT; kk += 16) {
            wmma::fragment<wmma::matrix_a, 16, 16, 16, half, wmma::row_major> a[2];
            wmma::fragment<wmma::matrix_b, 16, 16, 16, half, wmma::col_major> b[4];
#pragma unroll
            for (int i = 0; i < 2; i++)
                wmma::load_matrix_sync(a[i], &sA[(wm * 32 + i * 16) * 72 + kk], 72);
#pragma unroll
            for (int j = 0; j < 4; j++)
                wmma::load_matrix_sync(b[j], &sB[(wn * 64 + j * 16) * 72 + kk], 72);
#pragma unroll
            for (int i = 0; i < 2; i++)
#pragma unroll
                for (int j = 0; j < 4; j++)
                    wmma::mma_sync(c[i][j], a[i], b[j], c[i][j]);
        }
        __syncthreads();
    }

#pragma unroll
    for (int i = 0; i < 2; i++)
#pragma unroll
        for (int j = 0; j < 4; j++) {
            wmma::store_matrix_sync(&s_stage[wid * 320], c[i][j], 20, wmma::mem_row_major);
            __syncwarp();
            int rt = wm * 32 + i * 16;
            int ct = col0 + wn * 64 + j * 16;
#pragma unroll
            for (int t = lane; t < 256; t += 32) {
                int rr = t >> 4, cc = t & 15;
                int a = s_asn[rt + rr];
                if (a >= 0) {
                    g_ebuf[(size_t)a * HDIM + ct + cc] =
                        s_stage[wid * 320 + rr * 20 + cc] + b2[e * HDIM + ct + cc];
                }
            }
            __syncwarp();
        }
#endif
}

// ---------------- combine -----------------------------------------------------------
__global__ void combine_kernel(float* __restrict__ out) {
    const float* ew = out + (size_t)NTOK * HDIM;
    int stride = gridDim.x * blockDim.x;
    int n4 = NTOK * HDIM / 4;
    for (int v = blockIdx.x * blockDim.x + threadIdx.x; v < n4; v += stride) {
        int t  = v >> 8;
        int hc = v & 255;
        float w0 = ew[t * 4 + 0], w1v = ew[t * 4 + 1];
        float w2v = ew[t * 4 + 2], w3 = ew[t * 4 + 3];
        const float4* e0 = (const float4*)(g_ebuf + (size_t)(t * 4 + 0) * HDIM);
        const float4* e1 = (const float4*)(g_ebuf + (size_t)(t * 4 + 1) * HDIM);
        const float4* e2 = (const float4*)(g_ebuf + (size_t)(t * 4 + 2) * HDIM);
        const float4* e3 = (const float4*)(g_ebuf + (size_t)(t * 4 + 3) * HDIM);
        float4 r0 = e0[hc], r1 = e1[hc], r2 = e2[hc], r3 = e3[hc];
        float4 o;
        o.x = w0 * r0.x + w1v * r1.x + w2v * r2.x + w3 * r3.x;
        o.y = w0 * r0.y + w1v * r1.y + w2v * r2.y + w3 * r3.y;
        o.z = w0 * r0.z + w1v * r1.z + w2v * r2.z + w3 * r3.z;
        o.w = w0 * r0.w + w1v * r1.w + w2v * r2.w + w3 * r3.w;
        ((float4*)out)[v] = o;
    }
}

// ---------------- launch ------------------------------------------------------------
extern "C" void kernel_launch(void* const* d_in, const int* in_sizes, int n_in,
                              void* d_out, int out_size) {
    const float* x  = (const float*)d_in[0];
    const float* rw = (const float*)d_in[1];
    const float* rb = (const float*)d_in[2];
    const float* w1 = (const float*)d_in[3];
    const float* b1 = (const float*)d_in[4];
    const float* w2 = (const float*)d_in[5];
    const float* b2 = (const float*)d_in[6];
    float* out = (float*)d_out;

    cudaFuncSetAttribute(gemm1_kernel, cudaFuncAttributeMaxDynamicSharedMemorySize, SMEM_TOTAL);
    cudaFuncSetAttribute(gemm2_kernel, cudaFuncAttributeMaxDynamicSharedMemorySize, SMEM_TOTAL);

    zero_counts_kernel<<<1, 32>>>();
    cvt_x_kernel<<<1024, 256>>>(x);

    __half* w1h; cudaGetSymbolAddress((void**)&w1h, g_w1h);
    __half* w2h; cudaGetSymbolAddress((void**)&w2h, g_w2h);
    cvt_t_kernel<<<dim3(GUDIM / 32, HDIM / 32, NEXP), dim3(32, 8)>>>(w1, w1h, HDIM, GUDIM);
    cvt_t_kernel<<<dim3(HDIM / 32, IDIM / 32, NEXP), dim3(32, 8)>>>(w2, w2h, IDIM, HDIM);

    router_kernel<<<NTOK / 8, 256>>>(x, rw, rb, out + (size_t)NTOK * HDIM);

    gemm1_kernel<<<dim3(GUDIM / NT, NTOK / MT, NEXP), 256, SMEM_TOTAL>>>(b1);
    gemm2_kernel<<<dim3(HDIM  / NT, NTOK / MT, NEXP), 256, SMEM_TOTAL>>>(b2);

    combine_kernel<<<2048, 256>>>(out);
}

// round 4
// speedup vs baseline: 1.4300x; 1.0181x over previous
#include <cuda_runtime.h>
#include <cuda_fp16.h>
#include <mma.h>
#include <cstdint>
#include <math.h>

#if defined(__CUDA_ARCH_FEAT_SM103_ALL) || defined(__CUDA_ARCH_FEAT_SM100_ALL) || defined(__CUDA_ARCH_FEAT_SM101_ALL)
#define HAS_TC 1
#else
#define HAS_TC 0
#endif

#define NTOK  4096
#define HDIM  1024
#define IDIM  1024
#define NEXP  8
#define TOPK  4
#define GUDIM 2048

#define MT 128
#define NT 128
#define KT 64                    // halves per K-chunk
#define NCHUNK 16

// idesc: dtype=F32(1<<4), atype=btype=F16(0), N=128 -> (N/8)<<17, M=128 -> (M/16)<<24
#define IDESC_F16 ((1u << 4) | ((NT / 8) << 17) | ((MT / 16) << 24))

// tcgen05-path smem layout
#define SM_TOK    64
#define SM_BUF    1024
#define BUF_SZ    32768
// fallback-path smem layout: tiles padded to 72 halves/row (144B, 16B-aligned)
#define FB_TILE   18432                 // 128 * 72 * 2
#define FB_STAGE  (2 * FB_TILE)         // A + B
#define SMEM_TOTAL (1024 + 2 * FB_STAGE)   // 74752 >= tcgen05's 66560

// ---------------- device scratch ----------------------------------------------------
__device__ __align__(16) __half g_xh [(size_t)NTOK * HDIM];
__device__ __align__(16) __half g_w1h[(size_t)NEXP * GUDIM * HDIM];   // [e][n][k]
__device__ __align__(16) __half g_w2h[(size_t)NEXP * HDIM * IDIM];    // [e][n][k]
__device__ __align__(16) __half g_act[(size_t)NEXP * NTOK * IDIM];
__device__ __align__(16) float  g_ebuf[(size_t)NTOK * TOPK * HDIM];
__device__ int g_count[NEXP];
__device__ int g_assign[NEXP * NTOK];

// ---------------- helpers -----------------------------------------------------------
__device__ __forceinline__ uint32_t smem_u32(const void* p) {
    uint32_t a;
    asm("{ .reg .u64 t; cvta.to.shared.u64 t, %1; cvt.u32.u64 %0, t; }" : "=r"(a) : "l"(p));
    return a;
}
__device__ __forceinline__ uint32_t sw128(uint32_t off) {
    return off ^ ((off >> 3) & 0x70);
}

// cp.async (Ampere+, fine for compute_103 PTX target)
#define CPA16(dst, src)       asm volatile("cp.async.cg.shared.global [%0], [%1], 16;"     :: "r"(dst), "l"(src))
#define CPA16P(dst, src, sz)  asm volatile("cp.async.cg.shared.global [%0], [%1], 16, %2;" :: "r"(dst), "l"(src), "r"(sz))
#define CPA_COMMIT()          asm volatile("cp.async.commit_group;" ::: "memory")
#define CPA_WAIT(n)           asm volatile("cp.async.wait_group %0;" :: "n"(n) : "memory")

#if HAS_TC
__device__ __forceinline__ uint32_t elect_one() {
    uint32_t pred;
    asm volatile("{\n\t.reg .pred p;\n\telect.sync _|p, 0xFFFFFFFF;\n\t"
                 "selp.b32 %0, 1, 0, p;\n\t}" : "=r"(pred));
    return pred;
}
#define TC_ALLOC(sa, n)  asm volatile("tcgen05.alloc.cta_group::1.sync.aligned.shared::cta.b32 [%0], %1;" :: "r"(sa), "r"(n) : "memory")
#define TC_DEALLOC(t, n) asm volatile("tcgen05.dealloc.cta_group::1.sync.aligned.b32 %0, %1;" :: "r"(t), "r"(n))
#define TC_RELINQ()      asm volatile("tcgen05.relinquish_alloc_permit.cta_group::1.sync.aligned;")
#define TC_COMMIT(mb)    asm volatile("tcgen05.commit.cta_group::1.mbarrier::arrive::one.shared::cluster.b64 [%0];" :: "r"(mb) : "memory")
#define TC_FENCE_AFTER()  asm volatile("tcgen05.fence::after_thread_sync;" ::: "memory")
#define TC_FENCE_BEFORE() asm volatile("tcgen05.fence::before_thread_sync;" ::: "memory")
#define TC_WAIT_LD()     asm volatile("tcgen05.wait::ld.sync.aligned;" ::: "memory")
#define FENCE_ASYNC()    asm volatile("fence.proxy.async.shared::cta;" ::: "memory")
#define MBAR_INIT(mb, n) asm volatile("mbarrier.init.shared.b64 [%0], %1;" :: "r"(mb), "r"(n) : "memory")

__device__ __forceinline__ void mbar_wait(uint32_t mb, uint32_t parity) {
    uint32_t done;
    asm volatile("{\n\t.reg .pred p;\n\t"
                 "mbarrier.try_wait.parity.acquire.cta.shared::cta.b64 p, [%1], %2;\n\t"
                 "selp.b32 %0, 1, 0, p;\n\t}"
                 : "=r"(done) : "r"(mb), "r"(parity) : "memory");
    if (!done) {
        asm volatile("{\n\t.reg .pred P1;\n\t"
                     "W_%=:\n\t"
                     "mbarrier.try_wait.parity.acquire.cta.shared::cta.b64 P1, [%0], %1, 0x989680;\n\t"
                     "@P1 bra.uni D_%=;\n\t"
                     "bra.uni W_%=;\n\t"
                     "D_%=:\n\t}"
                     :: "r"(mb), "r"(parity) : "memory");
    }
}
__device__ __forceinline__ uint64_t make_desc(uint32_t addr) {
    return ((uint64_t)2 << 61) | ((uint64_t)1 << 46) | ((uint64_t)64 << 32) |
           ((uint64_t)1 << 16) | ((uint64_t)(addr >> 4) & 0x3FFF);
}
__device__ __forceinline__ void mma_f16_ss(uint32_t d, uint64_t ad, uint64_t bd,
                                           uint32_t idesc, uint32_t en) {
    asm volatile("{\n\t.reg .pred p;\n\t"
                 "setp.ne.u32 p, %5, 0;\n\t"
                 "tcgen05.mma.cta_group::1.kind::f16 [%0], %1, %2, %3, {%4, %4, %4, %4}, p;\n\t}"
                 :: "r"(d), "l"(ad), "l"(bd), "r"(idesc), "r"(0u), "r"(en)
                 : "memory");
}
#define TC_LD_X32(r, a) \
    asm volatile("tcgen05.ld.sync.aligned.32x32b.x32.b32 " \
        "{%0,%1,%2,%3,%4,%5,%6,%7,%8,%9,%10,%11,%12,%13,%14,%15," \
        "%16,%17,%18,%19,%20,%21,%22,%23,%24,%25,%26,%27,%28,%29,%30,%31}, [%32];" \
        : "=r"((r)[0]),"=r"((r)[1]),"=r"((r)[2]),"=r"((r)[3]),"=r"((r)[4]),"=r"((r)[5]),"=r"((r)[6]),"=r"((r)[7]), \
          "=r"((r)[8]),"=r"((r)[9]),"=r"((r)[10]),"=r"((r)[11]),"=r"((r)[12]),"=r"((r)[13]),"=r"((r)[14]),"=r"((r)[15]), \
          "=r"((r)[16]),"=r"((r)[17]),"=r"((r)[18]),"=r"((r)[19]),"=r"((r)[20]),"=r"((r)[21]),"=r"((r)[22]),"=r"((r)[23]), \
          "=r"((r)[24]),"=r"((r)[25]),"=r"((r)[26]),"=r"((r)[27]),"=r"((r)[28]),"=r"((r)[29]),"=r"((r)[30]),"=r"((r)[31]) \
        : "r"(a))
#endif  // HAS_TC

// ---------------- tiny utility kernels ----------------------------------------------
__global__ void zero_counts_kernel() {
    if (threadIdx.x < NEXP) g_count[threadIdx.x] = 0;
}

__global__ void cvt_x_kernel(const float* __restrict__ s) {
    int stride = gridDim.x * blockDim.x;
    int n4 = NTOK * HDIM / 4;
    for (int i = blockIdx.x * blockDim.x + threadIdx.x; i < n4; i += stride) {
        float4 v = ((const float4*)s)[i];
        __half2* d = (__half2*)(g_xh + (size_t)i * 4);
        d[0] = __floats2half2_rn(v.x, v.y);
        d[1] = __floats2half2_rn(v.z, v.w);
    }
}

// transpose-convert: s [z][K][N] fp32 -> d [z][N][K] fp16 (half2 coalesced writes)
__global__ void cvt_t_kernel(const float* __restrict__ s, __half* __restrict__ d,
                             int K, int N) {
    __shared__ float t[32][33];
    int n0 = blockIdx.x * 32, k0 = blockIdx.y * 32, z = blockIdx.z;
    const float* sp = s + (size_t)z * K * N;
    __half* dp = d + (size_t)z * K * N;
    int tx = threadIdx.x, ty = threadIdx.y;
#pragma unroll
    for (int i = 0; i < 32; i += 8)
        t[ty + i][tx] = sp[(size_t)(k0 + ty + i) * N + n0 + tx];
    __syncthreads();
    int id = ty * 32 + tx;
#pragma unroll
    for (int j = 0; j < 2; j++) {
        int v = id + j * 256;       // 0..511 half2 elements
        int r = v >> 4;             // output n-row 0..31
        int c = v & 15;             // half2 index along k
        __half2 h = __floats2half2_rn(t[c * 2][r], t[c * 2 + 1][r]);
        *(__half2*)(dp + (size_t)(n0 + r) * K + k0 + c * 2) = h;
    }
}

// ---------------- router ------------------------------------------------------------
__global__ void router_kernel(const float* __restrict__ x,
                              const float* __restrict__ rw,
                              const float* __restrict__ rb,
                              float* __restrict__ ew_out) {
    int warp = (blockIdx.x * blockDim.x + threadIdx.x) >> 5;
    int lane = threadIdx.x & 31;
    if (warp >= NTOK) return;
    const float* xr = x + (size_t)warp * HDIM;

    float acc[NEXP];
#pragma unroll
    for (int e = 0; e < NEXP; e++) acc[e] = 0.f;
    for (int h = lane; h < HDIM; h += 32) {
        float xv = xr[h];
#pragma unroll
        for (int e = 0; e < NEXP; e++) acc[e] += xv * rw[e * HDIM + h];
    }
#pragma unroll
    for (int e = 0; e < NEXP; e++) {
#pragma unroll
        for (int off = 16; off; off >>= 1)
            acc[e] += __shfl_xor_sync(0xffffffffu, acc[e], off);
    }
    if (lane == 0) {
        float lg[NEXP];
#pragma unroll
        for (int e = 0; e < NEXP; e++) lg[e] = acc[e] + rb[e];
        int idx[TOPK]; float val[TOPK]; bool used[NEXP];
#pragma unroll
        for (int e = 0; e < NEXP; e++) used[e] = false;
        for (int k = 0; k < TOPK; k++) {
            float best = -INFINITY; int bi = 0;
            for (int e = 0; e < NEXP; e++)
                if (!used[e] && lg[e] > best) { best = lg[e]; bi = e; }
            used[bi] = true; idx[k] = bi; val[k] = best;
        }
        float m = val[0], s = 0.f, w[TOPK];
        for (int k = 0; k < TOPK; k++) { w[k] = expf(val[k] - m); s += w[k]; }
        float inv = 1.f / s;
        for (int k = 0; k < TOPK; k++) {
            w[k] *= inv;
            ew_out[warp * TOPK + k] = w[k];
            int p = atomicAdd(&g_count[idx[k]], 1);
            g_assign[idx[k] * NTOK + p] = warp * 4 + k;
        }
    }
}

// ====================================================================================
// GEMM1: act = SwiGLU(gather(x) @ w1^T + b1)
// ====================================================================================
__global__ __launch_bounds__(256)
void gemm1_kernel(const float* __restrict__ b1) {
    extern __shared__ char smem[];
    const int e    = blockIdx.z;
    const int cnt  = g_count[e];
    const int row0 = blockIdx.y * MT;
    if (row0 >= cnt) return;
    const int col0 = blockIdx.x * NT;
    const int tid = threadIdx.x, lane = tid & 31, wid = tid >> 5;

#if HAS_TC
    uint32_t sb = smem_u32(smem);
    int* s_tok = (int*)(smem + SM_TOK);
    if (wid == 0) { TC_ALLOC(sb, 128); TC_RELINQ(); }
    if (tid == 0) { MBAR_INIT(sb + 8, 1); MBAR_INIT(sb + 16, 1); }
    if (tid < 128) {
        int r = row0 + tid;
        s_tok[tid] = (r < cnt) ? (g_assign[e * NTOK + r] >> 2) : -1;
    }
    __syncthreads();
    uint32_t tmem;
    asm volatile("ld.shared.b32 %0, [%1];" : "=r"(tmem) : "r"(sb));

    {
        char* bufA = smem + SM_BUF;
        char* bufB = bufA + 16384;
#pragma unroll
        for (int i = 0; i < 4; i++) {
            int v = tid + i * 256, r = v >> 3, c8 = v & 7;
            int tok = s_tok[r];
            float4 d = (tok >= 0) ? *(const float4*)(g_xh + (size_t)tok * HDIM + c8 * 8)
                                  : make_float4(0.f, 0.f, 0.f, 0.f);
            *(float4*)(bufA + sw128(r * 128 + c8 * 16)) = d;
            *(float4*)(bufB + sw128(r * 128 + c8 * 16)) =
                *(const float4*)(g_w1h + ((size_t)e * GUDIM + col0 + r) * HDIM + c8 * 8);
        }
    }
    __syncthreads();

    for (int c = 0; c < NCHUNK; c++) {
        int p = c & 1;
        if (wid == 0 && elect_one()) {
            FENCE_ASYNC();
            uint64_t ad = make_desc(sb + SM_BUF + p * BUF_SZ);
            uint64_t bd = make_desc(sb + SM_BUF + p * BUF_SZ + 16384);
#pragma unroll
            for (int s = 0; s < 4; s++)
                mma_f16_ss(tmem, ad + s * 2, bd + s * 2, IDESC_F16, (c > 0 || s > 0) ? 1u : 0u);
            TC_COMMIT(sb + 8 + p * 8);
        }
        if (c + 1 < NCHUNK) {
            int np = (c + 1) & 1;
            if (c + 1 >= 2) mbar_wait(sb + 8 + np * 8, (((c + 1) >> 1) - 1) & 1);
            int kt = (c + 1) * KT;
            char* bufA = smem + SM_BUF + np * BUF_SZ;
            char* bufB = bufA + 16384;
#pragma unroll
            for (int i = 0; i < 4; i++) {
                int v = tid + i * 256, r = v >> 3, c8 = v & 7;
                int tok = s_tok[r];
                float4 d = (tok >= 0) ? *(const float4*)(g_xh + (size_t)tok * HDIM + kt + c8 * 8)
                                      : make_float4(0.f, 0.f, 0.f, 0.f);
                *(float4*)(bufA + sw128(r * 128 + c8 * 16)) = d;
                *(float4*)(bufB + sw128(r * 128 + c8 * 16)) =
                    *(const float4*)(g_w1h + ((size_t)e * GUDIM + col0 + r) * HDIM + kt + c8 * 8);
            }
            __syncthreads();
        }
    }
    mbar_wait(sb + 8 + ((NCHUNK - 1) & 1) * 8, ((NCHUNK - 1) >> 1) & 1);
    TC_FENCE_AFTER();
    {
        int sub = wid & 3, ch = wid >> 2;
        int r = row0 + sub * 32 + lane;
        bool valid = (r < cnt);
        const float* bb = b1 + e * GUDIM + col0;
#pragma unroll
        for (int cbi = 0; cbi < 2; cbi++) {
            int cb = ch * 2 + cbi;
            uint32_t regs[32];
            TC_LD_X32(regs, tmem + cb * 32);
            TC_WAIT_LD();
            if (valid) {
                __align__(16) __half hv[16];
#pragma unroll
                for (int j = 0; j < 16; j++) {
                    float g = __uint_as_float(regs[2 * j])     + bb[cb * 32 + 2 * j];
                    float u = __uint_as_float(regs[2 * j + 1]) + bb[cb * 32 + 2 * j + 1];
                    g = fminf(g, 7.0f);
                    u = fminf(fmaxf(u, -7.0f), 7.0f);
                    float glu = g / (1.0f + expf(-1.702f * g));
                    hv[j] = __float2half((u + 1.0f) * glu);
                }
                __half* dst = g_act + ((size_t)e * NTOK + r) * IDIM + (col0 >> 1) + cb * 16;
                *(int4*)dst       = *(int4*)hv;
                *(int4*)(dst + 8) = *(int4*)(hv + 8);
            }
        }
    }
    TC_FENCE_BEFORE();
    __syncthreads();
    if (wid == 0) TC_DEALLOC(tmem, 128);

#else  // ---------------- wmma fallback with cp.async pipeline -----------------------
    using namespace nvcuda;
    int* s_tok = (int*)smem;
    uint32_t sb = smem_u32(smem);

    const int wm = wid >> 1, wn = wid & 1;
    if (tid < 128) {
        int r = row0 + tid;
        s_tok[tid] = (r < cnt) ? (g_assign[e * NTOK + r] >> 2) : -1;
    }
    __syncthreads();

    wmma::fragment<wmma::accumulator, 16, 16, 16, float> c[2][4];
#pragma unroll
    for (int i = 0; i < 2; i++)
#pragma unroll
        for (int j = 0; j < 4; j++) wmma::fill_fragment(c[i][j], 0.0f);

    const __half* Bb = g_w1h + ((size_t)e * GUDIM + col0) * HDIM;

    // per-thread load slots: 4 A rows + 4 B rows (each 16B)
    const int lr = tid >> 3, lc = tid & 7;          // covers v = tid + i*256

    // issue stage for chunk cidx into buffer p
    auto issue = [&](int cidx) {
        int p = cidx & 1;
        int kt = cidx * KT;
        uint32_t a0 = sb + 1024 + p * FB_STAGE;
        uint32_t b0 = a0 + FB_TILE;
#pragma unroll
        for (int i = 0; i < 4; i++) {
            int r = lr + i * 32;
            int tok = s_tok[r];
            const __half* srcA = g_xh + (size_t)(tok < 0 ? 0 : tok) * HDIM + kt + lc * 8;
            CPA16P(a0 + (r * 72 + lc * 8) * 2, srcA, (tok >= 0) ? 16 : 0);
            CPA16(b0 + (r * 72 + lc * 8) * 2, Bb + (size_t)r * HDIM + kt + lc * 8);
        }
        CPA_COMMIT();
    };

    issue(0);
    for (int cc = 0; cc < NCHUNK; cc++) {
        int p = cc & 1;
        if (cc + 1 < NCHUNK) { issue(cc + 1); CPA_WAIT(1); }
        else                 { CPA_WAIT(0); }
        __syncthreads();
        const __half* sA = (const __half*)(smem + 1024 + p * FB_STAGE);
        const __half* sB = sA + FB_TILE / 2;
#pragma unroll
        for (int kk = 0; kk < KT; kk += 16) {
            wmma::fragment<wmma::matrix_a, 16, 16, 16, half, wmma::row_major> a[2];
            wmma::fragment<wmma::matrix_b, 16, 16, 16, half, wmma::col_major> b[4];
#pragma unroll
            for (int i = 0; i < 2; i++)
                wmma::load_matrix_sync(a[i], &sA[(wm * 32 + i * 16) * 72 + kk], 72);
#pragma unroll
            for (int j = 0; j < 4; j++)
                wmma::load_matrix_sync(b[j], &sB[(wn * 64 + j * 16) * 72 + kk], 72);
#pragma unroll
            for (int i = 0; i < 2; i++)
#pragma unroll
                for (int j = 0; j < 4; j++)
                    wmma::mma_sync(c[i][j], a[i], b[j], c[i][j]);
        }
        __syncthreads();
    }

    float* s_stage = (float*)(smem + 1024);   // buffers dead now
#pragma unroll
    for (int i = 0; i < 2; i++)
#pragma unroll
        for (int j = 0; j < 4; j++) {
            wmma::store_matrix_sync(&s_stage[wid * 320], c[i][j], 20, wmma::mem_row_major);
            __syncwarp();
            int rt = wm * 32 + i * 16;
            int ct = col0 + wn * 64 + j * 16;
#pragma unroll
            for (int t = lane; t < 128; t += 32) {
                int rr = t >> 3, pp = t & 7;
                int r = row0 + rt + rr;
                if (r < cnt) {
                    int gc = ct + pp * 2;
                    float g = s_stage[wid * 320 + rr * 20 + pp * 2]     + b1[e * GUDIM + gc];
                    float u = s_stage[wid * 320 + rr * 20 + pp * 2 + 1] + b1[e * GUDIM + gc + 1];
                    g = fminf(g, 7.0f);
                    u = fminf(fmaxf(u, -7.0f), 7.0f);
                    float glu = g / (1.0f + expf(-1.702f * g));
                    g_act[((size_t)e * NTOK + r) * IDIM + (gc >> 1)] =
                        __float2half((u + 1.0f) * glu);
                }
            }
            __syncwarp();
        }
#endif
}

// ====================================================================================
// GEMM2: ebuf[assign] = act @ w2^T + b2
// ====================================================================================
__global__ __launch_bounds__(256)
void gemm2_kernel(const float* __restrict__ b2) {
    extern __shared__ char smem[];
    const int e    = blockIdx.z;
    const int cnt  = g_count[e];
    const int row0 = blockIdx.y * MT;
    if (row0 >= cnt) return;
    const int col0 = blockIdx.x * NT;
    const int tid = threadIdx.x, lane = tid & 31, wid = tid >> 5;

#if HAS_TC
    uint32_t sb = smem_u32(smem);
    int* s_asn = (int*)(smem + SM_TOK);
    if (wid == 0) { TC_ALLOC(sb, 128); TC_RELINQ(); }
    if (tid == 0) { MBAR_INIT(sb + 8, 1); MBAR_INIT(sb + 16, 1); }
    if (tid < 128) {
        int r = row0 + tid;
        s_asn[tid] = (r < cnt) ? g_assign[e * NTOK + r] : -1;
    }
    __syncthreads();
    uint32_t tmem;
    asm volatile("ld.shared.b32 %0, [%1];" : "=r"(tmem) : "r"(sb));

    const __half* Ab = g_act + ((size_t)e * NTOK + row0) * IDIM;
    const __half* Bb = g_w2h + (size_t)e * HDIM * IDIM + (size_t)col0 * IDIM;
    {
        char* bufA = smem + SM_BUF;
        char* bufB = bufA + 16384;
#pragma unroll
        for (int i = 0; i < 4; i++) {
            int v = tid + i * 256, r = v >> 3, c8 = v & 7;
            float4 d = (s_asn[r] >= 0) ? *(const float4*)(Ab + (size_t)r * IDIM + c8 * 8)
                                       : make_float4(0.f, 0.f, 0.f, 0.f);
            *(float4*)(bufA + sw128(r * 128 + c8 * 16)) = d;
            *(float4*)(bufB + sw128(r * 128 + c8 * 16)) =
                *(const float4*)(Bb + (size_t)r * IDIM + c8 * 8);
        }
    }
    __syncthreads();

    for (int c = 0; c < NCHUNK; c++) {
        int p = c & 1;
        if (wid == 0 && elect_one()) {
            FENCE_ASYNC();
            uint64_t ad = make_desc(sb + SM_BUF + p * BUF_SZ);
            uint64_t bd = make_desc(sb + SM_BUF + p * BUF_SZ + 16384);
#pragma unroll
            for (int s = 0; s < 4; s++)
                mma_f16_ss(tmem, ad + s * 2, bd + s * 2, IDESC_F16, (c > 0 || s > 0) ? 1u : 0u);
            TC_COMMIT(sb + 8 + p * 8);
        }
        if (c + 1 < NCHUNK) {
            int np = (c + 1) & 1;
            if (c + 1 >= 2) mbar_wait(sb + 8 + np * 8, (((c + 1) >> 1) - 1) & 1);
            int kt = (c + 1) * KT;
            char* bufA = smem + SM_BUF + np * BUF_SZ;
            char* bufB = bufA + 16384;
#pragma unroll
            for (int i = 0; i < 4; i++) {
                int v = tid + i * 256, r = v >> 3, c8 = v & 7;
                float4 d = (s_asn[r] >= 0) ? *(const float4*)(Ab + (size_t)r * IDIM + kt + c8 * 8)
                                           : make_float4(0.f, 0.f, 0.f, 0.f);
                *(float4*)(bufA + sw128(r * 128 + c8 * 16)) = d;
                *(float4*)(bufB + sw128(r * 128 + c8 * 16)) =
                    *(const float4*)(Bb + (size_t)r * IDIM + kt + c8 * 8);
            }
            __syncthreads();
        }
    }
    mbar_wait(sb + 8 + ((NCHUNK - 1) & 1) * 8, ((NCHUNK - 1) >> 1) & 1);
    TC_FENCE_AFTER();
    {
        int sub = wid & 3, ch = wid >> 2;
        int rloc = sub * 32 + lane;
        int a = (row0 + rloc < cnt) ? s_asn[rloc] : -1;
        const float* bb = b2 + e * HDIM + col0;
#pragma unroll
        for (int cbi = 0; cbi < 2; cbi++) {
            int cb = ch * 2 + cbi;
            uint32_t regs[32];
            TC_LD_X32(regs, tmem + cb * 32);
            TC_WAIT_LD();
            if (a >= 0) {
                float* dst = g_ebuf + (size_t)a * HDIM + col0 + cb * 32;
#pragma unroll
                for (int j = 0; j < 8; j++) {
                    float4 o;
                    o.x = __uint_as_float(regs[4 * j + 0]) + bb[cb * 32 + 4 * j + 0];
                    o.y = __uint_as_float(regs[4 * j + 1]) + bb[cb * 32 + 4 * j + 1];
                    o.z = __uint_as_float(regs[4 * j + 2]) + bb[cb * 32 + 4 * j + 2];
                    o.w = __uint_as_float(regs[4 * j + 3]) + bb[cb * 32 + 4 * j + 3];
                    *(float4*)(dst + 4 * j) = o;
                }
            }
        }
    }
    TC_FENCE_BEFORE();
    __syncthreads();
    if (wid == 0) TC_DEALLOC(tmem, 128);

#else  // ---------------- wmma fallback with cp.async pipeline -----------------------
    using namespace nvcuda;
    int* s_asn = (int*)smem;
    uint32_t sb = smem_u32(smem);

    const int wm = wid >> 1, wn = wid & 1;
    if (tid < 128) {
        int r = row0 + tid;
        s_asn[tid] = (r < cnt) ? g_assign[e * NTOK + r] : -1;
    }
    __syncthreads();

    wmma::fragment<wmma::accumulator, 16, 16, 16, float> c[2][4];
#pragma unroll
    for (int i = 0; i < 2; i++)
#pragma unroll
        for (int j = 0; j < 4; j++) wmma::fill_fragment(c[i][j], 0.0f);

    const __half* Ab = g_act + ((size_t)e * NTOK + row0) * IDIM;
    const __half* Bb = g_w2h + (size_t)e * HDIM * IDIM + (size_t)col0 * IDIM;

    const int lr = tid >> 3, lc = tid & 7;

    auto issue = [&](int cidx) {
        int p = cidx & 1;
        int kt = cidx * KT;
        uint32_t a0 = sb + 1024 + p * FB_STAGE;
        uint32_t b0 = a0 + FB_TILE;
#pragma unroll
        for (int i = 0; i < 4; i++) {
            int r = lr + i * 32;
            int ok = (s_asn[r] >= 0) ? 16 : 0;
            CPA16P(a0 + (r * 72 + lc * 8) * 2, Ab + (size_t)r * IDIM + kt + lc * 8, ok);
            CPA16(b0 + (r * 72 + lc * 8) * 2, Bb + (size_t)r * IDIM + kt + lc * 8);
        }
        CPA_COMMIT();
    };

    issue(0);
    for (int cc = 0; cc < NCHUNK; cc++) {
        int p = cc & 1;
        if (cc + 1 < NCHUNK) { issue(cc + 1); CPA_WAIT(1); }
        else                 { CPA_WAIT(0); }
        __syncthreads();
        const __half* sA = (const __half*)(smem + 1024 + p * FB_STAGE);
        const __half* sB = sA + FB_TILE / 2;
#pragma unroll
        for (int kk = 0; kk < KT; kk += 16) {
            wmma::fragment<wmma::matrix_a, 16, 16, 16, half, wmma::row_major> a[2];
            wmma::fragment<wmma::matrix_b, 16, 16, 16, half, wmma::col_major> b[4];
#pragma unroll
            for (int i = 0; i < 2; i++)
                wmma::load_matrix_sync(a[i], &sA[(wm * 32 + i * 16) * 72 + kk], 72);
#pragma unroll
            for (int j = 0; j < 4; j++)
                wmma::load_matrix_sync(b[j], &sB[(wn * 64 + j * 16) * 72 + kk], 72);
#pragma unroll
            for (int i = 0; i < 2; i++)
#pragma unroll
                for (int j = 0; j < 4; j++)
                    wmma::mma_sync(c[i][j], a[i], b[j], c[i][j]);
        }
        __syncthreads();
    }

    float* s_stage = (float*)(smem + 1024);
#pragma unroll
    for (int i = 0; i < 2; i++)
#pragma unroll
        for (int j = 0; j < 4; j++) {
            wmma::store_matrix_sync(&s_stage[wid * 320], c[i][j], 20, wmma::mem_row_major);
            __syncwarp();
            int rt = wm * 32 + i * 16;
            int ct = col0 + wn * 64 + j * 16;
#pragma unroll
            for (int t = lane; t < 256; t += 32) {
                int rr = t >> 4, cc2 = t & 15;
                int a = s_asn[rt + rr];
                if (a >= 0) {
                    g_ebuf[(size_t)a * HDIM + ct + cc2] =
                        s_stage[wid * 320 + rr * 20 + cc2] + b2[e * HDIM + ct + cc2];
                }
            }
            __syncwarp();
        }
#endif
}

// ---------------- combine -----------------------------------------------------------
__global__ void combine_kernel(float* __restrict__ out) {
    const float* ew = out + (size_t)NTOK * HDIM;
    int stride = gridDim.x * blockDim.x;
    int n4 = NTOK * HDIM / 4;
    for (int v = blockIdx.x * blockDim.x + threadIdx.x; v < n4; v += stride) {
        int t  = v >> 8;
        int hc = v & 255;
        float w0 = ew[t * 4 + 0], w1v = ew[t * 4 + 1];
        float w2v = ew[t * 4 + 2], w3 = ew[t * 4 + 3];
        const float4* e0 = (const float4*)(g_ebuf + (size_t)(t * 4 + 0) * HDIM);
        const float4* e1 = (const float4*)(g_ebuf + (size_t)(t * 4 + 1) * HDIM);
        const float4* e2 = (const float4*)(g_ebuf + (size_t)(t * 4 + 2) * HDIM);
        const float4* e3 = (const float4*)(g_ebuf + (size_t)(t * 4 + 3) * HDIM);
        float4 r0 = e0[hc], r1 = e1[hc], r2 = e2[hc], r3 = e3[hc];
        float4 o;
        o.x = w0 * r0.x + w1v * r1.x + w2v * r2.x + w3 * r3.x;
        o.y = w0 * r0.y + w1v * r1.y + w2v * r2.y + w3 * r3.y;
        o.z = w0 * r0.z + w1v * r1.z + w2v * r2.z + w3 * r3.z;
        o.w = w0 * r0.w + w1v * r1.w + w2v * r2.w + w3 * r3.w;
        ((float4*)out)[v] = o;
    }
}

// ---------------- launch ------------------------------------------------------------
extern "C" void kernel_launch(void* const* d_in, const int* in_sizes, int n_in,
                              void* d_out, int out_size) {
    const float* x  = (const float*)d_in[0];
    const float* rw = (const float*)d_in[1];
    const float* rb = (const float*)d_in[2];
    const float* w1 = (const float*)d_in[3];
    const float* b1 = (const float*)d_in[4];
    const float* w2 = (const float*)d_in[5];
    const float* b2 = (const float*)d_in[6];
    float* out = (float*)d_out;

    cudaFuncSetAttribute(gemm1_kernel, cudaFuncAttributeMaxDynamicSharedMemorySize, SMEM_TOTAL);
    cudaFuncSetAttribute(gemm2_kernel, cudaFuncAttributeMaxDynamicSharedMemorySize, SMEM_TOTAL);

    zero_counts_kernel<<<1, 32>>>();
    cvt_x_kernel<<<1024, 256>>>(x);

    __half* w1h; cudaGetSymbolAddress((void**)&w1h, g_w1h);
    __half* w2h; cudaGetSymbolAddress((void**)&w2h, g_w2h);
    cvt_t_kernel<<<dim3(GUDIM / 32, HDIM / 32, NEXP), dim3(32, 8)>>>(w1, w1h, HDIM, GUDIM);
    cvt_t_kernel<<<dim3(HDIM / 32, IDIM / 32, NEXP), dim3(32, 8)>>>(w2, w2h, IDIM, HDIM);

    router_kernel<<<NTOK / 8, 256>>>(x, rw, rb, out + (size_t)NTOK * HDIM);

    gemm1_kernel<<<dim3(GUDIM / NT, NTOK / MT, NEXP), 256, SMEM_TOTAL>>>(b1);
    gemm2_kernel<<<dim3(HDIM  / NT, NTOK / MT, NEXP), 256, SMEM_TOTAL>>>(b2);

    combine_kernel<<<2048, 256>>>(out);
}

// round 6
// speedup vs baseline: 1.9043x; 1.3317x over previous
#include <cuda_runtime.h>
#include <cuda_fp16.h>
#include <cstdint>
#include <math.h>

#define NTOK  4096
#define HDIM  1024
#define IDIM  1024
#define NEXP  8
#define TOPK  4
#define GUDIM 2048

#define MT 128
#define NT 128
#define KT 64
#define NCHUNK 16

// smem: [0,512) token/assign ints, buffers at 1024, 2 stages of (A+B) 72-half-pitch tiles
#define FB_TILE  (128 * 72 * 2)          // 18432 B
#define FB_STAGE (2 * FB_TILE)           // 36864 B
#define SMEM_TOTAL (1024 + 2 * FB_STAGE) // 74752 B -> 2 CTAs/SM

// ---------------- device scratch ----------------------------------------------------
__device__ __align__(16) __half g_xh [(size_t)NTOK * HDIM];
__device__ __align__(16) __half g_w1h[(size_t)NEXP * GUDIM * HDIM];   // [e][n][k]
__device__ __align__(16) __half g_w2h[(size_t)NEXP * HDIM * IDIM];    // [e][n][k]
__device__ __align__(16) __half g_act[(size_t)NEXP * NTOK * IDIM];
__device__ __align__(16) float  g_ebuf[(size_t)NTOK * TOPK * HDIM];
__device__ int g_count[NEXP];
__device__ int g_assign[NEXP * NTOK];

// ---------------- helpers -----------------------------------------------------------
__device__ __forceinline__ uint32_t smem_u32(const void* p) {
    uint32_t a;
    asm("{ .reg .u64 t; cvta.to.shared.u64 t, %1; cvt.u32.u64 %0, t; }" : "=r"(a) : "l"(p));
    return a;
}

#define CPA16(dst, src)       asm volatile("cp.async.cg.shared.global [%0], [%1], 16;"     :: "r"(dst), "l"(src))
#define CPA16P(dst, src, sz)  asm volatile("cp.async.cg.shared.global [%0], [%1], 16, %2;" :: "r"(dst), "l"(src), "r"(sz))
#define CPA_COMMIT()          asm volatile("cp.async.commit_group;" ::: "memory")
#define CPA_WAIT(n)           asm volatile("cp.async.wait_group %0;" :: "n"(n) : "memory")

__device__ __forceinline__ void ldsm4(uint32_t& r0, uint32_t& r1, uint32_t& r2, uint32_t& r3,
                                      uint32_t addr) {
    asm volatile("ldmatrix.sync.aligned.m8n8.x4.shared.b16 {%0,%1,%2,%3}, [%4];"
                 : "=r"(r0), "=r"(r1), "=r"(r2), "=r"(r3) : "r"(addr));
}
__device__ __forceinline__ void mma16816(float* d, const uint32_t* a, uint32_t b0, uint32_t b1) {
    asm volatile("mma.sync.aligned.m16n8k16.row.col.f32.f16.f16.f32 "
                 "{%0,%1,%2,%3},{%4,%5,%6,%7},{%8,%9},{%0,%1,%2,%3};"
                 : "+f"(d[0]), "+f"(d[1]), "+f"(d[2]), "+f"(d[3])
                 : "r"(a[0]), "r"(a[1]), "r"(a[2]), "r"(a[3]), "r"(b0), "r"(b1));
}

// ---------------- tiny utility kernels ----------------------------------------------
__global__ void zero_counts_kernel() {
    if (threadIdx.x < NEXP) g_count[threadIdx.x] = 0;
}

__global__ void cvt_x_kernel(const float* __restrict__ s) {
    int stride = gridDim.x * blockDim.x;
    int n4 = NTOK * HDIM / 4;
    for (int i = blockIdx.x * blockDim.x + threadIdx.x; i < n4; i += stride) {
        float4 v = ((const float4*)s)[i];
        __half2* d = (__half2*)(g_xh + (size_t)i * 4);
        d[0] = __floats2half2_rn(v.x, v.y);
        d[1] = __floats2half2_rn(v.z, v.w);
    }
}

// transpose-convert: s [z][K][N] fp32 -> d [z][N][K] fp16 (half2 coalesced writes)
__global__ void cvt_t_kernel(const float* __restrict__ s, __half* __restrict__ d,
                             int K, int N) {
    __shared__ float t[32][33];
    int n0 = blockIdx.x * 32, k0 = blockIdx.y * 32, z = blockIdx.z;
    const float* sp = s + (size_t)z * K * N;
    __half* dp = d + (size_t)z * K * N;
    int tx = threadIdx.x, ty = threadIdx.y;
#pragma unroll
    for (int i = 0; i < 32; i += 8)
        t[ty + i][tx] = sp[(size_t)(k0 + ty + i) * N + n0 + tx];
    __syncthreads();
    int id = ty * 32 + tx;
#pragma unroll
    for (int j = 0; j < 2; j++) {
        int v = id + j * 256;
        int r = v >> 4;
        int c = v & 15;
        __half2 h = __floats2half2_rn(t[c * 2][r], t[c * 2 + 1][r]);
        *(__half2*)(dp + (size_t)(n0 + r) * K + k0 + c * 2) = h;
    }
}

// ---------------- router ------------------------------------------------------------
__global__ void router_kernel(const float* __restrict__ x,
                              const float* __restrict__ rw,
                              const float* __restrict__ rb,
                              float* __restrict__ ew_out) {
    int warp = (blockIdx.x * blockDim.x + threadIdx.x) >> 5;
    int lane = threadIdx.x & 31;
    if (warp >= NTOK) return;
    const float* xr = x + (size_t)warp * HDIM;

    float acc[NEXP];
#pragma unroll
    for (int e = 0; e < NEXP; e++) acc[e] = 0.f;
    for (int h = lane; h < HDIM; h += 32) {
        float xv = xr[h];
#pragma unroll
        for (int e = 0; e < NEXP; e++) acc[e] += xv * rw[e * HDIM + h];
    }
#pragma unroll
    for (int e = 0; e < NEXP; e++) {
#pragma unroll
        for (int off = 16; off; off >>= 1)
            acc[e] += __shfl_xor_sync(0xffffffffu, acc[e], off);
    }
    if (lane == 0) {
        float lg[NEXP];
#pragma unroll
        for (int e = 0; e < NEXP; e++) lg[e] = acc[e] + rb[e];
        int idx[TOPK]; float val[TOPK]; bool used[NEXP];
#pragma unroll
        for (int e = 0; e < NEXP; e++) used[e] = false;
        for (int k = 0; k < TOPK; k++) {
            float best = -INFINITY; int bi = 0;
            for (int e = 0; e < NEXP; e++)
                if (!used[e] && lg[e] > best) { best = lg[e]; bi = e; }
            used[bi] = true; idx[k] = bi; val[k] = best;
        }
        float m = val[0], s = 0.f, w[TOPK];
        for (int k = 0; k < TOPK; k++) { w[k] = expf(val[k] - m); s += w[k]; }
        float inv = 1.f / s;
        for (int k = 0; k < TOPK; k++) {
            w[k] *= inv;
            ew_out[warp * TOPK + k] = w[k];
            int p = atomicAdd(&g_count[idx[k]], 1);
            g_assign[idx[k] * NTOK + p] = warp * 4 + k;
        }
    }
}

// ====================================================================================
// GEMM1: act = SwiGLU(gather(x) @ w1^T + b1)   (128 thr, 4 warps, warp tile 64x64)
// ====================================================================================
__global__ __launch_bounds__(128, 2)
void gemm1_kernel(const float* __restrict__ b1) {
    extern __shared__ char smem[];
    const int e    = blockIdx.z;
    const int cnt  = g_count[e];
    const int row0 = blockIdx.y * MT;
    if (row0 >= cnt) return;
    const int col0 = blockIdx.x * NT;
    const int tid = threadIdx.x, lane = tid & 31, wid = tid >> 5;
    const int wm = wid >> 1, wn = wid & 1;
    uint32_t sb = smem_u32(smem);
    int* s_tok = (int*)smem;

    {
        int r = row0 + tid;
        s_tok[tid] = (r < cnt) ? (g_assign[e * NTOK + r] >> 2) : -1;
    }
    __syncthreads();

    float d[4][8][4];
#pragma unroll
    for (int mi = 0; mi < 4; mi++)
#pragma unroll
        for (int nt = 0; nt < 8; nt++)
#pragma unroll
            for (int r = 0; r < 4; r++) d[mi][nt][r] = 0.f;

    const __half* Bb = g_w1h + ((size_t)e * GUDIM + col0) * HDIM;
    const int lr = tid >> 3, lc = tid & 7;   // 16 rows-per-pass x 8 col-slots

    auto issue = [&](int cidx) {
        int p = cidx & 1, kt = cidx * KT;
        uint32_t a0 = sb + 1024 + p * FB_STAGE;
        uint32_t b0 = a0 + FB_TILE;
#pragma unroll
        for (int i = 0; i < 8; i++) {
            int r = lr + i * 16;
            int tok = s_tok[r];
            CPA16P(a0 + (r * 72 + lc * 8) * 2,
                   g_xh + (size_t)(tok < 0 ? 0 : tok) * HDIM + kt + lc * 8,
                   (tok >= 0) ? 16 : 0);
            CPA16(b0 + (r * 72 + lc * 8) * 2, Bb + (size_t)r * HDIM + kt + lc * 8);
        }
        CPA_COMMIT();
    };

    issue(0);
    for (int cc = 0; cc < NCHUNK; cc++) {
        int p = cc & 1;
        if (cc + 1 < NCHUNK) { issue(cc + 1); CPA_WAIT(1); }
        else                 { CPA_WAIT(0); }
        __syncthreads();
        uint32_t sA = sb + 1024 + p * FB_STAGE;
        uint32_t sB = sA + FB_TILE;
        uint32_t aBase = sA + ((wm * 64 + (lane & 15)) * 72 + (lane >> 4) * 8) * 2;
        uint32_t bBase = sB + ((wn * 64 + (lane & 7) + (lane >> 4) * 8) * 72 +
                               ((lane >> 3) & 1) * 8) * 2;
#pragma unroll
        for (int kk = 0; kk < KT; kk += 16) {
            uint32_t a[4][4], b[4][4];
#pragma unroll
            for (int mi = 0; mi < 4; mi++)
                ldsm4(a[mi][0], a[mi][1], a[mi][2], a[mi][3],
                      aBase + (mi * 16 * 72 + kk) * 2);
#pragma unroll
            for (int g = 0; g < 4; g++)
                ldsm4(b[g][0], b[g][1], b[g][2], b[g][3],
                      bBase + (g * 16 * 72 + kk) * 2);
#pragma unroll
            for (int mi = 0; mi < 4; mi++)
#pragma unroll
                for (int g = 0; g < 4; g++) {
                    mma16816(d[mi][2 * g],     a[mi], b[g][0], b[g][1]);
                    mma16816(d[mi][2 * g + 1], a[mi], b[g][2], b[g][3]);
                }
        }
        __syncthreads();
    }

    // stage accumulators (pitch 132 floats)
    float* st = (float*)(smem + 1024);
#pragma unroll
    for (int mi = 0; mi < 4; mi++)
#pragma unroll
        for (int nt = 0; nt < 8; nt++)
#pragma unroll
            for (int r = 0; r < 4; r++) {
                int row = wm * 64 + mi * 16 + (lane >> 2) + 8 * (r >> 1);
                int col = wn * 64 + nt * 8 + (lane & 3) * 2 + (r & 1);
                st[row * 132 + col] = d[mi][nt][r];
            }
    __syncthreads();

    int rg = row0 + tid;
    if (rg < cnt) {
        const float* bb = b1 + e * GUDIM + col0;
        __align__(16) __half hv[64];
#pragma unroll
        for (int c = 0; c < 64; c++) {
            float g = st[tid * 132 + 2 * c]     + bb[2 * c];
            float u = st[tid * 132 + 2 * c + 1] + bb[2 * c + 1];
            g = fminf(g, 7.0f);
            u = fminf(fmaxf(u, -7.0f), 7.0f);
            float glu = g / (1.0f + expf(-1.702f * g));
            hv[c] = __float2half((u + 1.0f) * glu);
        }
        __half* dst = g_act + ((size_t)e * NTOK + rg) * IDIM + (col0 >> 1);
#pragma unroll
        for (int j = 0; j < 8; j++)
            *(int4*)(dst + j * 8) = *(int4*)(hv + j * 8);
    }
}

// ====================================================================================
// GEMM2: ebuf[assign] = act @ w2^T + b2   (same engine)
// ====================================================================================
__global__ __launch_bounds__(128, 2)
void gemm2_kernel(const float* __restrict__ b2) {
    extern __shared__ char smem[];
    const int e    = blockIdx.z;
    const int cnt  = g_count[e];
    const int row0 = blockIdx.y * MT;
    if (row0 >= cnt) return;
    const int col0 = blockIdx.x * NT;
    const int tid = threadIdx.x, lane = tid & 31, wid = tid >> 5;
    const int wm = wid >> 1, wn = wid & 1;
    uint32_t sb = smem_u32(smem);
    int* s_asn = (int*)smem;

    {
        int r = row0 + tid;
        s_asn[tid] = (r < cnt) ? g_assign[e * NTOK + r] : -1;
    }
    __syncthreads();

    float d[4][8][4];
#pragma unroll
    for (int mi = 0; mi < 4; mi++)
#pragma unroll
        for (int nt = 0; nt < 8; nt++)
#pragma unroll
            for (int r = 0; r < 4; r++) d[mi][nt][r] = 0.f;

    const __half* Ab = g_act + ((size_t)e * NTOK + row0) * IDIM;
    const __half* Bb = g_w2h + (size_t)e * HDIM * IDIM + (size_t)col0 * IDIM;
    const int lr = tid >> 3, lc = tid & 7;

    auto issue = [&](int cidx) {
        int p = cidx & 1, kt = cidx * KT;
        uint32_t a0 = sb + 1024 + p * FB_STAGE;
        uint32_t b0 = a0 + FB_TILE;
#pragma unroll
        for (int i = 0; i < 8; i++) {
            int r = lr + i * 16;
            int ok = (s_asn[r] >= 0) ? 16 : 0;
            CPA16P(a0 + (r * 72 + lc * 8) * 2, Ab + (size_t)r * IDIM + kt + lc * 8, ok);
            CPA16(b0 + (r * 72 + lc * 8) * 2, Bb + (size_t)r * IDIM + kt + lc * 8);
        }
        CPA_COMMIT();
    };

    issue(0);
    for (int cc = 0; cc < NCHUNK; cc++) {
        int p = cc & 1;
        if (cc + 1 < NCHUNK) { issue(cc + 1); CPA_WAIT(1); }
        else                 { CPA_WAIT(0); }
        __syncthreads();
        uint32_t sA = sb + 1024 + p * FB_STAGE;
        uint32_t sB = sA + FB_TILE;
        uint32_t aBase = sA + ((wm * 64 + (lane & 15)) * 72 + (lane >> 4) * 8) * 2;
        uint32_t bBase = sB + ((wn * 64 + (lane & 7) + (lane >> 4) * 8) * 72 +
                               ((lane >> 3) & 1) * 8) * 2;
#pragma unroll
        for (int kk = 0; kk < KT; kk += 16) {
            uint32_t a[4][4], b[4][4];
#pragma unroll
            for (int mi = 0; mi < 4; mi++)
                ldsm4(a[mi][0], a[mi][1], a[mi][2], a[mi][3],
                      aBase + (mi * 16 * 72 + kk) * 2);
#pragma unroll
            for (int g = 0; g < 4; g++)
                ldsm4(b[g][0], b[g][1], b[g][2], b[g][3],
                      bBase + (g * 16 * 72 + kk) * 2);
#pragma unroll
            for (int mi = 0; mi < 4; mi++)
#pragma unroll
                for (int g = 0; g < 4; g++) {
                    mma16816(d[mi][2 * g],     a[mi], b[g][0], b[g][1]);
                    mma16816(d[mi][2 * g + 1], a[mi], b[g][2], b[g][3]);
                }
        }
        __syncthreads();
    }

    float* st = (float*)(smem + 1024);
#pragma unroll
    for (int mi = 0; mi < 4; mi++)
#pragma unroll
        for (int nt = 0; nt < 8; nt++)
#pragma unroll
            for (int r = 0; r < 4; r++) {
                int row = wm * 64 + mi * 16 + (lane >> 2) + 8 * (r >> 1);
                int col = wn * 64 + nt * 8 + (lane & 3) * 2 + (r & 1);
                st[row * 132 + col] = d[mi][nt][r];
            }
    __syncthreads();

    int a = s_asn[tid];
    if (a >= 0) {
        const float* bb = b2 + e * HDIM + col0;
        float* dst = g_ebuf + (size_t)a * HDIM + col0;
#pragma unroll
        for (int j = 0; j < 32; j++) {
            float4 o;
            o.x = st[tid * 132 + 4 * j + 0] + bb[4 * j + 0];
            o.y = st[tid * 132 + 4 * j + 1] + bb[4 * j + 1];
            o.z = st[tid * 132 + 4 * j + 2] + bb[4 * j + 2];
            o.w = st[tid * 132 + 4 * j + 3] + bb[4 * j + 3];
            *(float4*)(dst + 4 * j) = o;
        }
    }
}

// ---------------- combine -----------------------------------------------------------
__global__ void combine_kernel(float* __restrict__ out) {
    const float* ew = out + (size_t)NTOK * HDIM;
    int stride = gridDim.x * blockDim.x;
    int n4 = NTOK * HDIM / 4;
    for (int v = blockIdx.x * blockDim.x + threadIdx.x; v < n4; v += stride) {
        int t  = v >> 8;
        int hc = v & 255;
        float w0 = ew[t * 4 + 0], w1v = ew[t * 4 + 1];
        float w2v = ew[t * 4 + 2], w3 = ew[t * 4 + 3];
        const float4* e0 = (const float4*)(g_ebuf + (size_t)(t * 4 + 0) * HDIM);
        const float4* e1 = (const float4*)(g_ebuf + (size_t)(t * 4 + 1) * HDIM);
        const float4* e2 = (const float4*)(g_ebuf + (size_t)(t * 4 + 2) * HDIM);
        const float4* e3 = (const float4*)(g_ebuf + (size_t)(t * 4 + 3) * HDIM);
        float4 r0 = e0[hc], r1 = e1[hc], r2 = e2[hc], r3 = e3[hc];
        float4 o;
        o.x = w0 * r0.x + w1v * r1.x + w2v * r2.x + w3 * r3.x;
        o.y = w0 * r0.y + w1v * r1.y + w2v * r2.y + w3 * r3.y;
        o.z = w0 * r0.z + w1v * r1.z + w2v * r2.z + w3 * r3.z;
        o.w = w0 * r0.w + w1v * r1.w + w2v * r2.w + w3 * r3.w;
        ((float4*)out)[v] = o;
    }
}

// ---------------- launch ------------------------------------------------------------
extern "C" void kernel_launch(void* const* d_in, const int* in_sizes, int n_in,
                              void* d_out, int out_size) {
    const float* x  = (const float*)d_in[0];
    const float* rw = (const float*)d_in[1];
    const float* rb = (const float*)d_in[2];
    const float* w1 = (const float*)d_in[3];
    const float* b1 = (const float*)d_in[4];
    const float* w2 = (const float*)d_in[5];
    const float* b2 = (const float*)d_in[6];
    float* out = (float*)d_out;

    cudaFuncSetAttribute(gemm1_kernel, cudaFuncAttributeMaxDynamicSharedMemorySize, SMEM_TOTAL);
    cudaFuncSetAttribute(gemm2_kernel, cudaFuncAttributeMaxDynamicSharedMemorySize, SMEM_TOTAL);

    zero_counts_kernel<<<1, 32>>>();
    cvt_x_kernel<<<1024, 256>>>(x);

    __half* w1h; cudaGetSymbolAddress((void**)&w1h, g_w1h);
    __half* w2h; cudaGetSymbolAddress((void**)&w2h, g_w2h);
    cvt_t_kernel<<<dim3(GUDIM / 32, HDIM / 32, NEXP), dim3(32, 8)>>>(w1, w1h, HDIM, GUDIM);
    cvt_t_kernel<<<dim3(HDIM / 32, IDIM / 32, NEXP), dim3(32, 8)>>>(w2, w2h, IDIM, HDIM);

    router_kernel<<<NTOK / 8, 256>>>(x, rw, rb, out + (size_t)NTOK * HDIM);

    gemm1_kernel<<<dim3(GUDIM / NT, NTOK / MT, NEXP), 128, SMEM_TOTAL>>>(b1);
    gemm2_kernel<<<dim3(HDIM  / NT, NTOK / MT, NEXP), 128, SMEM_TOTAL>>>(b2);

    combine_kernel<<<2048, 256>>>(out);
}